// round 11
// baseline (speedup 1.0000x reference)
#include <cuda_runtime.h>
#include <math.h>
#include <stdint.h>

#define NMAX 100000
#define EMAX 1600000
#define HDIM 128
#define C_OUT 20

// ---- static device scratch (no allocation allowed) ----
__device__ float4 g_agg[(size_t)NMAX * HDIM / 4];   // aggregation / temp buffer
__device__ float4 g_h[(size_t)NMAX * HDIM / 4];     // layer activations
__device__ int    g_hist[NMAX];
__device__ int    g_rowptr[NMAX + 1];
__device__ int    g_wofs[NMAX];
__device__ int    g_srcs[EMAX];
__device__ int    g_bsum[128];

// ================= helpers =================

__device__ __forceinline__ uint32_t cvt_tf32(float f) {
    uint32_t u;
    asm("cvt.rna.tf32.f32 %0, %1;" : "=r"(u) : "f"(f));
    return u;
}

// D = A(16x8, tf32 row) * B(8x8, tf32 col) + C, fp32 accum
__device__ __forceinline__ void mma_tf32(float* c, const uint32_t* a, const uint32_t* b) {
    asm volatile(
        "mma.sync.aligned.m16n8k8.row.col.f32.tf32.tf32.f32 "
        "{%0,%1,%2,%3}, {%4,%5,%6,%7}, {%8,%9}, {%0,%1,%2,%3};"
        : "+f"(c[0]), "+f"(c[1]), "+f"(c[2]), "+f"(c[3])
        : "r"(a[0]), "r"(a[1]), "r"(a[2]), "r"(a[3]),
          "r"(b[0]), "r"(b[1]));
}

// ================= CSR build (edge_index is device-resident int32) =================

__global__ void k_zero_hist(int n) {
    int i = blockIdx.x * blockDim.x + threadIdx.x;
    if (i < n) g_hist[i] = 0;
}

__global__ void k_hist(const int* __restrict__ ei, int e, int n) {
    int i = blockIdx.x * blockDim.x + threadIdx.x;
    if (i < e) {
        int d = ei[e + i];
        if ((unsigned)d < (unsigned)n) atomicAdd(&g_hist[d], 1);
    }
}

__global__ void k_scan1(int n) {
    __shared__ int sh[512];
    int b = blockIdx.x, t = threadIdx.x;
    int base = b * 2048 + t * 4;
    int s = 0;
#pragma unroll
    for (int i = 0; i < 4; i++) {
        int idx = base + i;
        if (idx < n) s += g_hist[idx];
    }
    sh[t] = s;
    __syncthreads();
    for (int off = 256; off > 0; off >>= 1) {
        if (t < off) sh[t] += sh[t + off];
        __syncthreads();
    }
    if (t == 0) g_bsum[b] = sh[0];
}

__global__ void k_scan2(int nb, int n) {
    __shared__ int sh[128];
    int t = threadIdx.x;
    int v = (t < nb) ? g_bsum[t] : 0;
    sh[t] = v;
    __syncthreads();
    for (int off = 1; off < 128; off <<= 1) {
        int a = (t >= off) ? sh[t - off] : 0;
        __syncthreads();
        sh[t] += a;
        __syncthreads();
    }
    int ex = (t == 0) ? 0 : sh[t - 1];
    if (t < nb) g_bsum[t] = ex;
    if (t == 127) g_rowptr[n] = sh[127];
}

__global__ void k_scan3(int n) {
    __shared__ int sh[512];
    int b = blockIdx.x, t = threadIdx.x;
    int base = b * 2048 + t * 4;
    int v[4];
    int s = 0;
#pragma unroll
    for (int i = 0; i < 4; i++) {
        int idx = base + i;
        v[i] = (idx < n) ? g_hist[idx] : 0;
        s += v[i];
    }
    sh[t] = s;
    __syncthreads();
    for (int off = 1; off < 512; off <<= 1) {
        int a = (t >= off) ? sh[t - off] : 0;
        __syncthreads();
        sh[t] += a;
        __syncthreads();
    }
    int run = g_bsum[b] + ((t == 0) ? 0 : sh[t - 1]);
#pragma unroll
    for (int i = 0; i < 4; i++) {
        int idx = base + i;
        if (idx < n) {
            g_rowptr[idx] = run;
            g_wofs[idx] = run;
            run += v[i];
        }
    }
}

__global__ void k_scatter(const int* __restrict__ ei, int e, int n) {
    int i = blockIdx.x * blockDim.x + threadIdx.x;
    if (i < e) {
        int d = ei[e + i];
        int s = ei[i];
        if ((unsigned)d < (unsigned)n && (unsigned)s < (unsigned)n) {
            int pos = atomicAdd(&g_wofs[d], 1);
            if ((unsigned)pos < (unsigned)EMAX) g_srcs[pos] = s;
        }
    }
}

// ================= mean aggregation: warp per node (x2 unroll — do NOT widen) =================

template <bool SRC_X>
__global__ void k_aggregate(const float4* __restrict__ xin, int n) {
    const float4* X = SRC_X ? xin : (const float4*)g_h;
    int w = (blockIdx.x * blockDim.x + threadIdx.x) >> 5;
    int lane = threadIdx.x & 31;
    if (w >= n) return;
    int beg = g_rowptr[w], end = g_rowptr[w + 1];
    float4 acc = make_float4(0.f, 0.f, 0.f, 0.f);
    int e = beg;
    for (; e + 1 < end; e += 2) {
        int s0 = g_srcs[e], s1 = g_srcs[e + 1];
        float4 v0 = X[(size_t)s0 * 32 + lane];
        float4 v1 = X[(size_t)s1 * 32 + lane];
        acc.x += v0.x + v1.x; acc.y += v0.y + v1.y;
        acc.z += v0.z + v1.z; acc.w += v0.w + v1.w;
    }
    if (e < end) {
        int s0 = g_srcs[e];
        float4 v0 = X[(size_t)s0 * 32 + lane];
        acc.x += v0.x; acc.y += v0.y; acc.z += v0.z; acc.w += v0.w;
    }
    int cnt = end - beg;
    float inv = 1.0f / (float)(cnt > 0 ? cnt : 1);
    float4 r = make_float4(acc.x * inv, acc.y * inv, acc.z * inv, acc.w * inv);
    g_agg[(size_t)w * 32 + lane] = r;
}

// ================= tf32 mma.sync GEMM (R7 structure) =================
// C[tile 128 x 128] = relu( Am @ Wl^T [+ Ax @ Wr^T] + bias )
// MODE 2 fuses the head: out = sigmoid( C @ Wm2^T + bm2 ) -> d_out.
// 256 threads = 8 warps (4M x 2N), warp tile 32x64, m16n8k8 fragments.

#define SROW 132   // padded row length (floats), conflict-free fragment LDS

template <int MODE>
__global__ __launch_bounds__(256, 1) void k_mmagemm(
    const float4* __restrict__ xparam,
    const float4* __restrict__ Wl, const float4* __restrict__ Wr,
    const float* __restrict__ bias,
    const float* __restrict__ Wm2, const float* __restrict__ bm2,
    float* __restrict__ outp, int n)
{
    constexpr bool DUAL = (MODE != 2);
    extern __shared__ uint32_t smem[];           // sA[128*SROW] then sW[128*SROW]
    uint32_t* sA = smem;
    uint32_t* sW = smem + 128 * SROW;
    __shared__ float sbias[128];

    const float4* Am4 = (MODE == 2) ? (const float4*)g_h : (const float4*)g_agg;
    const float4* Ax4 = (MODE == 0) ? xparam : (const float4*)g_h;
    float* Cout = (float*)g_h;

    int tid = threadIdx.x;
    int lane = tid & 31, wid = tid >> 5;
    int wm = wid >> 1, wn = wid & 1;             // warp grid 4 x 2
    int g = lane >> 2, t = lane & 3;
    int row0 = blockIdx.x * 128;

    if (tid < 128) sbias[tid] = bias[tid];

    float c[2][8][4];
#pragma unroll
    for (int mi = 0; mi < 2; mi++)
#pragma unroll
        for (int ni = 0; ni < 8; ni++)
#pragma unroll
            for (int q = 0; q < 4; q++) c[mi][ni][q] = 0.f;

    const int NPASS = DUAL ? 2 : 1;
    for (int pass = 0; pass < NPASS; pass++) {
        const float4* Asrc = (pass == 0) ? Am4 : Ax4;
        const float4* Wsrc = (pass == 0) ? Wl : Wr;
        __syncthreads();   // previous pass consumers done before overwrite
        // ---- stage A (128 x 128) and W (128 x 128) as tf32, coalesced ----
        for (int i = tid; i < 4096; i += 256) {
            int r = i >> 5, kq = i & 31;         // one warp = one row (32 float4)
            int grow = row0 + r;
            float4 v = make_float4(0.f, 0.f, 0.f, 0.f);
            if (grow < n) v = Asrc[(size_t)grow * 32 + kq];
            uint32_t* pa = sA + r * SROW + kq * 4;
            pa[0] = cvt_tf32(v.x); pa[1] = cvt_tf32(v.y);
            pa[2] = cvt_tf32(v.z); pa[3] = cvt_tf32(v.w);
            float4 w = Wsrc[i];
            uint32_t* pw = sW + r * SROW + kq * 4;
            pw[0] = cvt_tf32(w.x); pw[1] = cvt_tf32(w.y);
            pw[2] = cvt_tf32(w.z); pw[3] = cvt_tf32(w.w);
        }
        __syncthreads();

        // ---- K loop: 16 steps of k8 ----
#pragma unroll
        for (int k0 = 0; k0 < 128; k0 += 8) {
            uint32_t a[2][4];
#pragma unroll
            for (int mi = 0; mi < 2; mi++) {
                int rb = wm * 32 + mi * 16;
                const uint32_t* p0 = sA + (rb + g) * SROW + k0 + t;
                const uint32_t* p1 = sA + (rb + 8 + g) * SROW + k0 + t;
                a[mi][0] = p0[0]; a[mi][1] = p1[0];
                a[mi][2] = p0[4]; a[mi][3] = p1[4];
            }
            uint32_t b[8][2];
#pragma unroll
            for (int ni = 0; ni < 8; ni++) {
                const uint32_t* p = sW + (wn * 64 + ni * 8 + g) * SROW + k0 + t;
                b[ni][0] = p[0]; b[ni][1] = p[4];
            }
#pragma unroll
            for (int mi = 0; mi < 2; mi++)
#pragma unroll
                for (int ni = 0; ni < 8; ni++)
                    mma_tf32(c[mi][ni], a[mi], b[ni]);
        }
    }
    __syncthreads();

    if (MODE != 2) {
        // ---- epilogue: bias + relu -> g_h ----
#pragma unroll
        for (int mi = 0; mi < 2; mi++) {
#pragma unroll
            for (int h = 0; h < 2; h++) {
                int row = row0 + wm * 32 + mi * 16 + h * 8 + g;
                if (row >= n) continue;
                float* dst = Cout + (size_t)row * 128;
#pragma unroll
                for (int ni = 0; ni < 8; ni++) {
                    int col = wn * 64 + ni * 8 + 2 * t;
                    float2 o;
                    o.x = fmaxf(c[mi][ni][h * 2 + 0] + sbias[col], 0.f);
                    o.y = fmaxf(c[mi][ni][h * 2 + 1] + sbias[col + 1], 0.f);
                    *(float2*)(dst + col) = o;
                }
            }
        }
    } else {
        // ---- fused head: t1 = relu(C+bias) staged in smem (reuse sA);
        //      out = sigmoid( t1 @ Wm2^T + bm2 ) -> d_out ----
        float* sOut = (float*)sA;                 // 128 x SROW floats
        float* sW2 = (float*)sW;                  // 20 x 128 floats
        float* sb2 = sW2 + C_OUT * 128;           // 20 floats
#pragma unroll
        for (int mi = 0; mi < 2; mi++)
#pragma unroll
            for (int h = 0; h < 2; h++) {
                int rl = wm * 32 + mi * 16 + h * 8 + g;
#pragma unroll
                for (int ni = 0; ni < 8; ni++) {
                    int col = wn * 64 + ni * 8 + 2 * t;
                    float2 o;
                    o.x = fmaxf(c[mi][ni][h * 2 + 0] + sbias[col], 0.f);
                    o.y = fmaxf(c[mi][ni][h * 2 + 1] + sbias[col + 1], 0.f);
                    *(float2*)(sOut + rl * SROW + col) = o;
                }
            }
        for (int i = tid; i < C_OUT * 128; i += 256) sW2[i] = Wm2[i];
        if (tid < C_OUT) sb2[tid] = bm2[tid];
        __syncthreads();

        // warp-per-row: 16 rows/warp, 20 outputs in 2 groups of 10 with
        // weights hoisted to registers (read smem weights once per group).
#pragma unroll
        for (int gr = 0; gr < 2; gr++) {
            float4 wv[10];
#pragma unroll
            for (int o = 0; o < 10; o++)
                wv[o] = *((const float4*)(sW2 + (gr * 10 + o) * 128) + lane);
            for (int r = 0; r < 16; r++) {
                int rl = wid * 16 + r;
                int grow = row0 + rl;
                if (grow >= n) continue;
                float4 hv = *((const float4*)(sOut + rl * SROW) + lane);
#pragma unroll
                for (int o = 0; o < 10; o++) {
                    float p = hv.x * wv[o].x + hv.y * wv[o].y +
                              hv.z * wv[o].z + hv.w * wv[o].w;
                    p += __shfl_xor_sync(0xFFFFFFFFu, p, 16);
                    p += __shfl_xor_sync(0xFFFFFFFFu, p, 8);
                    p += __shfl_xor_sync(0xFFFFFFFFu, p, 4);
                    p += __shfl_xor_sync(0xFFFFFFFFu, p, 2);
                    p += __shfl_xor_sync(0xFFFFFFFFu, p, 1);
                    int oc = gr * 10 + o;
                    if (lane == oc) {
                        float z = p + sb2[oc];
                        outp[(size_t)grow * C_OUT + oc] = 1.f / (1.f + __expf(-z));
                    }
                }
            }
        }
    }
}

// ================= launch =================

extern "C" void kernel_launch(void* const* d_in, const int* in_sizes, int n_in,
                              void* d_out, int out_size)
{
    const float* x   = (const float*)d_in[0];
    const int*   ei  = (const int*)d_in[1];
    const float* W1l = (const float*)d_in[2];
    const float* b1  = (const float*)d_in[3];
    const float* W1r = (const float*)d_in[4];
    const float* W2l = (const float*)d_in[5];
    const float* b2  = (const float*)d_in[6];
    const float* W2r = (const float*)d_in[7];
    const float* Wm1 = (const float*)d_in[8];
    const float* bm1 = (const float*)d_in[9];
    const float* Wm2 = (const float*)d_in[10];
    const float* bm2 = (const float*)d_in[11];
    float* out = (float*)d_out;

    int n = in_sizes[0] / HDIM;
    int e = in_sizes[1] / 2;
    int ntiles = (n + 127) / 128;

    const int SMEM_GEMM = 2 * 128 * SROW * 4;   // 135168 B
    cudaFuncSetAttribute(k_mmagemm<0>, cudaFuncAttributeMaxDynamicSharedMemorySize, SMEM_GEMM);
    cudaFuncSetAttribute(k_mmagemm<1>, cudaFuncAttributeMaxDynamicSharedMemorySize, SMEM_GEMM);
    cudaFuncSetAttribute(k_mmagemm<2>, cudaFuncAttributeMaxDynamicSharedMemorySize, SMEM_GEMM);

    // CSR build
    k_zero_hist<<<(n + 255) / 256, 256>>>(n);
    k_hist<<<(e + 255) / 256, 256>>>(ei, e, n);
    int nb = (n + 2047) / 2048;
    k_scan1<<<nb, 512>>>(n);
    k_scan2<<<1, 128>>>(nb, n);
    k_scan3<<<nb, 512>>>(n);
    k_scatter<<<(e + 255) / 256, 256>>>(ei, e, n);

    int aggBlocks = (n + 7) / 8;

    // layer 1
    k_aggregate<true><<<aggBlocks, 256>>>((const float4*)x, n);
    k_mmagemm<0><<<ntiles, 256, SMEM_GEMM>>>((const float4*)x, (const float4*)W1l,
                                             (const float4*)W1r, b1,
                                             nullptr, nullptr, nullptr, n);
    // layer 2
    k_aggregate<false><<<aggBlocks, 256>>>(nullptr, n);
    k_mmagemm<1><<<ntiles, 256, SMEM_GEMM>>>(nullptr, (const float4*)W2l,
                                             (const float4*)W2r, b2,
                                             nullptr, nullptr, nullptr, n);
    // MLP layer + fused sigmoid head -> d_out
    k_mmagemm<2><<<ntiles, 256, SMEM_GEMM>>>(nullptr, (const float4*)Wm1, nullptr, bm1,
                                             Wm2, bm2, out, n);
}

// round 12
// speedup vs baseline: 1.9048x; 1.9048x over previous
#include <cuda_runtime.h>
#include <math.h>
#include <stdint.h>

#define NMAX 100000
#define EMAX 1600000
#define HDIM 128
#define C_OUT 20

// ---- static device scratch (no allocation allowed) ----
__device__ float4 g_agg[(size_t)NMAX * HDIM / 4];   // aggregation / temp buffer
__device__ float4 g_h[(size_t)NMAX * HDIM / 4];     // layer activations
__device__ int    g_hist[NMAX];
__device__ int    g_rowptr[NMAX + 1];
__device__ int    g_wofs[NMAX];
__device__ int    g_srcs[EMAX];
__device__ int    g_bsum[128];

// ================= helpers =================

__device__ __forceinline__ uint32_t cvt_tf32(float f) {
    uint32_t u;
    asm("cvt.rna.tf32.f32 %0, %1;" : "=r"(u) : "f"(f));
    return u;
}

// D = A(16x8, tf32 row) * B(8x8, tf32 col) + C, fp32 accum
__device__ __forceinline__ void mma_tf32(float* c, const uint32_t* a, const uint32_t* b) {
    asm volatile(
        "mma.sync.aligned.m16n8k8.row.col.f32.tf32.tf32.f32 "
        "{%0,%1,%2,%3}, {%4,%5,%6,%7}, {%8,%9}, {%0,%1,%2,%3};"
        : "+f"(c[0]), "+f"(c[1]), "+f"(c[2]), "+f"(c[3])
        : "r"(a[0]), "r"(a[1]), "r"(a[2]), "r"(a[3]),
          "r"(b[0]), "r"(b[1]));
}

// ================= CSR build (edge_index is device-resident int32) =================

__global__ void k_zero_hist(int n) {
    int i = blockIdx.x * blockDim.x + threadIdx.x;
    if (i < n) g_hist[i] = 0;
}

__global__ void k_hist(const int* __restrict__ ei, int e, int n) {
    int i = blockIdx.x * blockDim.x + threadIdx.x;
    if (i < e) {
        int d = ei[e + i];
        if ((unsigned)d < (unsigned)n) atomicAdd(&g_hist[d], 1);
    }
}

__global__ void k_scan1(int n) {
    __shared__ int sh[512];
    int b = blockIdx.x, t = threadIdx.x;
    int base = b * 2048 + t * 4;
    int s = 0;
#pragma unroll
    for (int i = 0; i < 4; i++) {
        int idx = base + i;
        if (idx < n) s += g_hist[idx];
    }
    sh[t] = s;
    __syncthreads();
    for (int off = 256; off > 0; off >>= 1) {
        if (t < off) sh[t] += sh[t + off];
        __syncthreads();
    }
    if (t == 0) g_bsum[b] = sh[0];
}

__global__ void k_scan2(int nb, int n) {
    __shared__ int sh[128];
    int t = threadIdx.x;
    int v = (t < nb) ? g_bsum[t] : 0;
    sh[t] = v;
    __syncthreads();
    for (int off = 1; off < 128; off <<= 1) {
        int a = (t >= off) ? sh[t - off] : 0;
        __syncthreads();
        sh[t] += a;
        __syncthreads();
    }
    int ex = (t == 0) ? 0 : sh[t - 1];
    if (t < nb) g_bsum[t] = ex;
    if (t == 127) g_rowptr[n] = sh[127];
}

__global__ void k_scan3(int n) {
    __shared__ int sh[512];
    int b = blockIdx.x, t = threadIdx.x;
    int base = b * 2048 + t * 4;
    int v[4];
    int s = 0;
#pragma unroll
    for (int i = 0; i < 4; i++) {
        int idx = base + i;
        v[i] = (idx < n) ? g_hist[idx] : 0;
        s += v[i];
    }
    sh[t] = s;
    __syncthreads();
    for (int off = 1; off < 512; off <<= 1) {
        int a = (t >= off) ? sh[t - off] : 0;
        __syncthreads();
        sh[t] += a;
        __syncthreads();
    }
    int run = g_bsum[b] + ((t == 0) ? 0 : sh[t - 1]);
#pragma unroll
    for (int i = 0; i < 4; i++) {
        int idx = base + i;
        if (idx < n) {
            g_rowptr[idx] = run;
            g_wofs[idx] = run;
            run += v[i];
        }
    }
}

__global__ void k_scatter(const int* __restrict__ ei, int e, int n) {
    int i = blockIdx.x * blockDim.x + threadIdx.x;
    if (i < e) {
        int d = ei[e + i];
        int s = ei[i];
        if ((unsigned)d < (unsigned)n && (unsigned)s < (unsigned)n) {
            int pos = atomicAdd(&g_wofs[d], 1);
            if ((unsigned)pos < (unsigned)EMAX) g_srcs[pos] = s;
        }
    }
}

// ================= mean aggregation: warp per node (x2 unroll) =================

template <bool SRC_X>
__global__ void k_aggregate(const float4* __restrict__ xin, int n) {
    const float4* X = SRC_X ? xin : (const float4*)g_h;
    int w = (blockIdx.x * blockDim.x + threadIdx.x) >> 5;
    int lane = threadIdx.x & 31;
    if (w >= n) return;
    int beg = g_rowptr[w], end = g_rowptr[w + 1];
    float4 acc = make_float4(0.f, 0.f, 0.f, 0.f);
    int e = beg;
    for (; e + 1 < end; e += 2) {
        int s0 = g_srcs[e], s1 = g_srcs[e + 1];
        float4 v0 = X[(size_t)s0 * 32 + lane];
        float4 v1 = X[(size_t)s1 * 32 + lane];
        acc.x += v0.x + v1.x; acc.y += v0.y + v1.y;
        acc.z += v0.z + v1.z; acc.w += v0.w + v1.w;
    }
    if (e < end) {
        int s0 = g_srcs[e];
        float4 v0 = X[(size_t)s0 * 32 + lane];
        acc.x += v0.x; acc.y += v0.y; acc.z += v0.z; acc.w += v0.w;
    }
    int cnt = end - beg;
    float inv = 1.0f / (float)(cnt > 0 ? cnt : 1);
    float4 r = make_float4(acc.x * inv, acc.y * inv, acc.z * inv, acc.w * inv);
    g_agg[(size_t)w * 32 + lane] = r;
}

// ================= tf32 mma.sync GEMM, K split in half for occupancy 2 =================
// C[tile 128 x 128] = relu( Am @ Wl^T [+ Ax @ Wr^T] + bias )
// 256 threads = 8 warps (4M x 2N), warp tile 32x64, m16n8k8 fragments.
// smem per buffer: 128 x 68 floats; A+W = 69.6 KB -> 2 blocks/SM.
// MODE 0: Am=g_agg, Ax=xparam, out=g_h   (layer 1, dual)
// MODE 1: Am=g_agg, Ax=g_h,    out=g_h   (layer 2, dual)
// MODE 2: Am=g_h,   single,    out=g_agg (MLP layer)

#define SROW2 68   // padded half-K row length (floats), conflict-free fragment LDS

template <int MODE>
__global__ __launch_bounds__(256, 2) void k_mmagemm(
    const float4* __restrict__ xparam,
    const float4* __restrict__ Wl, const float4* __restrict__ Wr,
    const float* __restrict__ bias, int n)
{
    constexpr bool DUAL = (MODE != 2);
    extern __shared__ uint32_t smem[];           // sA[128*SROW2] then sW[128*SROW2]
    uint32_t* sA = smem;
    uint32_t* sW = smem + 128 * SROW2;
    __shared__ float sbias[128];

    const float4* Am4 = (MODE == 2) ? (const float4*)g_h : (const float4*)g_agg;
    const float4* Ax4 = (MODE == 0) ? xparam : (const float4*)g_h;
    float* Cout = (MODE == 2) ? (float*)g_agg : (float*)g_h;

    int tid = threadIdx.x;
    int lane = tid & 31, wid = tid >> 5;
    int wm = wid >> 1, wn = wid & 1;             // warp grid 4 x 2
    int g = lane >> 2, t = lane & 3;
    int row0 = blockIdx.x * 128;

    if (tid < 128) sbias[tid] = bias[tid];

    float c[2][8][4];
#pragma unroll
    for (int mi = 0; mi < 2; mi++)
#pragma unroll
        for (int ni = 0; ni < 8; ni++)
#pragma unroll
            for (int q = 0; q < 4; q++) c[mi][ni][q] = 0.f;

    const int NPASS = DUAL ? 2 : 1;
    for (int pass = 0; pass < NPASS; pass++) {
        const float4* Asrc = (pass == 0) ? Am4 : Ax4;
        const float4* Wsrc = (pass == 0) ? Wl : Wr;
#pragma unroll
        for (int half = 0; half < 2; half++) {
            __syncthreads();   // previous compute consumers done before overwrite
            // ---- stage A half (128 x 64) and W half (128 x 64) as tf32 ----
            for (int i = tid; i < 2048; i += 256) {
                int r = i >> 4, kq = i & 15;     // 16 float4 per row-half
                int grow = row0 + r;
                float4 v = make_float4(0.f, 0.f, 0.f, 0.f);
                if (grow < n) v = Asrc[(size_t)grow * 32 + half * 16 + kq];
                uint32_t* pa = sA + r * SROW2 + kq * 4;
                pa[0] = cvt_tf32(v.x); pa[1] = cvt_tf32(v.y);
                pa[2] = cvt_tf32(v.z); pa[3] = cvt_tf32(v.w);
                float4 w = Wsrc[(size_t)r * 32 + half * 16 + kq];
                uint32_t* pw = sW + r * SROW2 + kq * 4;
                pw[0] = cvt_tf32(w.x); pw[1] = cvt_tf32(w.y);
                pw[2] = cvt_tf32(w.z); pw[3] = cvt_tf32(w.w);
            }
            __syncthreads();

            // ---- K loop: 8 steps of k8 over this half ----
#pragma unroll
            for (int k0 = 0; k0 < 64; k0 += 8) {
                uint32_t a[2][4];
#pragma unroll
                for (int mi = 0; mi < 2; mi++) {
                    int rb = wm * 32 + mi * 16;
                    const uint32_t* p0 = sA + (rb + g) * SROW2 + k0 + t;
                    const uint32_t* p1 = sA + (rb + 8 + g) * SROW2 + k0 + t;
                    a[mi][0] = p0[0]; a[mi][1] = p1[0];
                    a[mi][2] = p0[4]; a[mi][3] = p1[4];
                }
                uint32_t b[8][2];
#pragma unroll
                for (int ni = 0; ni < 8; ni++) {
                    const uint32_t* p = sW + (wn * 64 + ni * 8 + g) * SROW2 + k0 + t;
                    b[ni][0] = p[0]; b[ni][1] = p[4];
                }
#pragma unroll
                for (int mi = 0; mi < 2; mi++)
#pragma unroll
                    for (int ni = 0; ni < 8; ni++)
                        mma_tf32(c[mi][ni], a[mi], b[ni]);
            }
        }
    }
    __syncthreads();

    // ---- epilogue: bias + relu, float2 stores ----
#pragma unroll
    for (int mi = 0; mi < 2; mi++) {
#pragma unroll
        for (int h = 0; h < 2; h++) {
            int row = row0 + wm * 32 + mi * 16 + h * 8 + g;
            if (row >= n) continue;
            float* dst = Cout + (size_t)row * 128;
#pragma unroll
            for (int ni = 0; ni < 8; ni++) {
                int col = wn * 64 + ni * 8 + 2 * t;
                float2 o;
                o.x = fmaxf(c[mi][ni][h * 2 + 0] + sbias[col], 0.f);
                o.y = fmaxf(c[mi][ni][h * 2 + 1] + sbias[col + 1], 0.f);
                *(float2*)(dst + col) = o;
            }
        }
    }
}

// ================= head: out = sigmoid(g_agg @ Wm2^T + bm2) =================

__global__ void k_head(const float* __restrict__ Wm2,
                       const float* __restrict__ bm2, float* __restrict__ out, int n)
{
    __shared__ __align__(16) float sW[C_OUT * HDIM];
    __shared__ float sb[C_OUT];
    int t = threadIdx.x;
    for (int i = t; i < C_OUT * HDIM; i += blockDim.x) sW[i] = Wm2[i];
    if (t < C_OUT) sb[t] = bm2[t];
    __syncthreads();

    const float4* T1 = (const float4*)g_agg;
    int warp_id = (blockIdx.x * blockDim.x + t) >> 5;
    int lane = t & 31;

    for (int v = 0; v < 4; v++) {
        int node = warp_id * 4 + v;
        if (node >= n) return;
        float4 h = T1[(size_t)node * 32 + lane];
#pragma unroll
        for (int o = 0; o < C_OUT; o++) {
            float4 wv = *((const float4*)(sW + o * HDIM) + lane);
            float p = h.x * wv.x + h.y * wv.y + h.z * wv.z + h.w * wv.w;
            p += __shfl_xor_sync(0xFFFFFFFFu, p, 16);
            p += __shfl_xor_sync(0xFFFFFFFFu, p, 8);
            p += __shfl_xor_sync(0xFFFFFFFFu, p, 4);
            p += __shfl_xor_sync(0xFFFFFFFFu, p, 2);
            p += __shfl_xor_sync(0xFFFFFFFFu, p, 1);
            if (lane == o) {
                float z = p + sb[o];
                out[(size_t)node * C_OUT + o] = 1.f / (1.f + __expf(-z));
            }
        }
    }
}

// ================= launch =================

extern "C" void kernel_launch(void* const* d_in, const int* in_sizes, int n_in,
                              void* d_out, int out_size)
{
    const float* x   = (const float*)d_in[0];
    const int*   ei  = (const int*)d_in[1];
    const float* W1l = (const float*)d_in[2];
    const float* b1  = (const float*)d_in[3];
    const float* W1r = (const float*)d_in[4];
    const float* W2l = (const float*)d_in[5];
    const float* b2  = (const float*)d_in[6];
    const float* W2r = (const float*)d_in[7];
    const float* Wm1 = (const float*)d_in[8];
    const float* bm1 = (const float*)d_in[9];
    const float* Wm2 = (const float*)d_in[10];
    const float* bm2 = (const float*)d_in[11];
    float* out = (float*)d_out;

    int n = in_sizes[0] / HDIM;
    int e = in_sizes[1] / 2;
    int ntiles = (n + 127) / 128;

    const int SMEM_GEMM = 2 * 128 * SROW2 * 4;   // 69632 B -> 2 blocks/SM
    cudaFuncSetAttribute(k_mmagemm<0>, cudaFuncAttributeMaxDynamicSharedMemorySize, SMEM_GEMM);
    cudaFuncSetAttribute(k_mmagemm<1>, cudaFuncAttributeMaxDynamicSharedMemorySize, SMEM_GEMM);
    cudaFuncSetAttribute(k_mmagemm<2>, cudaFuncAttributeMaxDynamicSharedMemorySize, SMEM_GEMM);

    // CSR build
    k_zero_hist<<<(n + 255) / 256, 256>>>(n);
    k_hist<<<(e + 255) / 256, 256>>>(ei, e, n);
    int nb = (n + 2047) / 2048;
    k_scan1<<<nb, 512>>>(n);
    k_scan2<<<1, 128>>>(nb, n);
    k_scan3<<<nb, 512>>>(n);
    k_scatter<<<(e + 255) / 256, 256>>>(ei, e, n);

    int aggBlocks = (n + 7) / 8;

    // layer 1
    k_aggregate<true><<<aggBlocks, 256>>>((const float4*)x, n);
    k_mmagemm<0><<<ntiles, 256, SMEM_GEMM>>>((const float4*)x, (const float4*)W1l,
                                             (const float4*)W1r, b1, n);
    // layer 2
    k_aggregate<false><<<aggBlocks, 256>>>(nullptr, n);
    k_mmagemm<1><<<ntiles, 256, SMEM_GEMM>>>(nullptr, (const float4*)W2l,
                                             (const float4*)W2r, b2, n);
    // MLP layer
    k_mmagemm<2><<<ntiles, 256, SMEM_GEMM>>>(nullptr, (const float4*)Wm1, nullptr, bm1, n);
    // head
    int headBlocks = (n + 31) / 32;
    k_head<<<headBlocks, 256>>>(Wm2, bm2, out, n);
}

// round 13
// speedup vs baseline: 1.9129x; 1.0043x over previous
#include <cuda_runtime.h>
#include <math.h>
#include <stdint.h>

#define NMAX 100000
#define EMAX 1600000
#define HDIM 128
#define C_OUT 20

// ---- static device scratch (no allocation allowed) ----
__device__ float4 g_agg[(size_t)NMAX * HDIM / 4];   // aggregation / temp buffer
__device__ float4 g_h[(size_t)NMAX * HDIM / 4];     // layer activations
__device__ int    g_hist[NMAX];
__device__ int    g_rowptr[NMAX + 1];
__device__ int    g_wofs[NMAX];
__device__ int    g_srcs[EMAX];
__device__ int    g_bsum[128];

// ================= helpers =================

__device__ __forceinline__ uint32_t cvt_tf32(float f) {
    uint32_t u;
    asm("cvt.rna.tf32.f32 %0, %1;" : "=r"(u) : "f"(f));
    return u;
}

// D = A(16x8, tf32 row) * B(8x8, tf32 col) + C, fp32 accum
__device__ __forceinline__ void mma_tf32(float* c, const uint32_t* a, const uint32_t* b) {
    asm volatile(
        "mma.sync.aligned.m16n8k8.row.col.f32.tf32.tf32.f32 "
        "{%0,%1,%2,%3}, {%4,%5,%6,%7}, {%8,%9}, {%0,%1,%2,%3};"
        : "+f"(c[0]), "+f"(c[1]), "+f"(c[2]), "+f"(c[3])
        : "r"(a[0]), "r"(a[1]), "r"(a[2]), "r"(a[3]),
          "r"(b[0]), "r"(b[1]));
}

// ================= CSR build (edge_index is device-resident int32) =================

__global__ void k_zero_hist(int n) {
    int i = blockIdx.x * blockDim.x + threadIdx.x;
    if (i < n) g_hist[i] = 0;
}

__global__ void k_hist(const int* __restrict__ ei, int e, int n) {
    int i = blockIdx.x * blockDim.x + threadIdx.x;
    if (i < e) {
        int d = ei[e + i];
        if ((unsigned)d < (unsigned)n) atomicAdd(&g_hist[d], 1);
    }
}

__global__ void k_scan1(int n) {
    __shared__ int sh[512];
    int b = blockIdx.x, t = threadIdx.x;
    int base = b * 2048 + t * 4;
    int s = 0;
#pragma unroll
    for (int i = 0; i < 4; i++) {
        int idx = base + i;
        if (idx < n) s += g_hist[idx];
    }
    sh[t] = s;
    __syncthreads();
    for (int off = 256; off > 0; off >>= 1) {
        if (t < off) sh[t] += sh[t + off];
        __syncthreads();
    }
    if (t == 0) g_bsum[b] = sh[0];
}

__global__ void k_scan2(int nb, int n) {
    __shared__ int sh[128];
    int t = threadIdx.x;
    int v = (t < nb) ? g_bsum[t] : 0;
    sh[t] = v;
    __syncthreads();
    for (int off = 1; off < 128; off <<= 1) {
        int a = (t >= off) ? sh[t - off] : 0;
        __syncthreads();
        sh[t] += a;
        __syncthreads();
    }
    int ex = (t == 0) ? 0 : sh[t - 1];
    if (t < nb) g_bsum[t] = ex;
    if (t == 127) g_rowptr[n] = sh[127];
}

__global__ void k_scan3(int n) {
    __shared__ int sh[512];
    int b = blockIdx.x, t = threadIdx.x;
    int base = b * 2048 + t * 4;
    int v[4];
    int s = 0;
#pragma unroll
    for (int i = 0; i < 4; i++) {
        int idx = base + i;
        v[i] = (idx < n) ? g_hist[idx] : 0;
        s += v[i];
    }
    sh[t] = s;
    __syncthreads();
    for (int off = 1; off < 512; off <<= 1) {
        int a = (t >= off) ? sh[t - off] : 0;
        __syncthreads();
        sh[t] += a;
        __syncthreads();
    }
    int run = g_bsum[b] + ((t == 0) ? 0 : sh[t - 1]);
#pragma unroll
    for (int i = 0; i < 4; i++) {
        int idx = base + i;
        if (idx < n) {
            g_rowptr[idx] = run;
            g_wofs[idx] = run;
            run += v[i];
        }
    }
}

__global__ void k_scatter(const int* __restrict__ ei, int e, int n) {
    int i = blockIdx.x * blockDim.x + threadIdx.x;
    if (i < e) {
        int d = ei[e + i];
        int s = ei[i];
        if ((unsigned)d < (unsigned)n && (unsigned)s < (unsigned)n) {
            int pos = atomicAdd(&g_wofs[d], 1);
            if ((unsigned)pos < (unsigned)EMAX) g_srcs[pos] = s;
        }
    }
}

// ================= mean aggregation: warp per node (x4 unroll — isolated test) =================

template <bool SRC_X>
__global__ void k_aggregate(const float4* __restrict__ xin, int n) {
    const float4* X = SRC_X ? xin : (const float4*)g_h;
    int w = (blockIdx.x * blockDim.x + threadIdx.x) >> 5;
    int lane = threadIdx.x & 31;
    if (w >= n) return;
    int beg = g_rowptr[w], end = g_rowptr[w + 1];
    float4 acc = make_float4(0.f, 0.f, 0.f, 0.f);
    int e = beg;
    for (; e + 3 < end; e += 4) {
        int s0 = g_srcs[e], s1 = g_srcs[e + 1], s2 = g_srcs[e + 2], s3 = g_srcs[e + 3];
        float4 v0 = X[(size_t)s0 * 32 + lane];
        float4 v1 = X[(size_t)s1 * 32 + lane];
        float4 v2 = X[(size_t)s2 * 32 + lane];
        float4 v3 = X[(size_t)s3 * 32 + lane];
        acc.x += (v0.x + v1.x) + (v2.x + v3.x);
        acc.y += (v0.y + v1.y) + (v2.y + v3.y);
        acc.z += (v0.z + v1.z) + (v2.z + v3.z);
        acc.w += (v0.w + v1.w) + (v2.w + v3.w);
    }
    for (; e < end; e++) {
        int s0 = g_srcs[e];
        float4 v0 = X[(size_t)s0 * 32 + lane];
        acc.x += v0.x; acc.y += v0.y; acc.z += v0.z; acc.w += v0.w;
    }
    int cnt = end - beg;
    float inv = 1.0f / (float)(cnt > 0 ? cnt : 1);
    float4 r = make_float4(acc.x * inv, acc.y * inv, acc.z * inv, acc.w * inv);
    g_agg[(size_t)w * 32 + lane] = r;
}

// ================= tf32 mma.sync GEMM, K split in half for occupancy 2 =================
// (byte-identical to R12 — known good at 391 us)

#define SROW2 68   // padded half-K row length (floats), conflict-free fragment LDS

template <int MODE>
__global__ __launch_bounds__(256, 2) void k_mmagemm(
    const float4* __restrict__ xparam,
    const float4* __restrict__ Wl, const float4* __restrict__ Wr,
    const float* __restrict__ bias, int n)
{
    constexpr bool DUAL = (MODE != 2);
    extern __shared__ uint32_t smem[];           // sA[128*SROW2] then sW[128*SROW2]
    uint32_t* sA = smem;
    uint32_t* sW = smem + 128 * SROW2;
    __shared__ float sbias[128];

    const float4* Am4 = (MODE == 2) ? (const float4*)g_h : (const float4*)g_agg;
    const float4* Ax4 = (MODE == 0) ? xparam : (const float4*)g_h;
    float* Cout = (MODE == 2) ? (float*)g_agg : (float*)g_h;

    int tid = threadIdx.x;
    int lane = tid & 31, wid = tid >> 5;
    int wm = wid >> 1, wn = wid & 1;             // warp grid 4 x 2
    int g = lane >> 2, t = lane & 3;
    int row0 = blockIdx.x * 128;

    if (tid < 128) sbias[tid] = bias[tid];

    float c[2][8][4];
#pragma unroll
    for (int mi = 0; mi < 2; mi++)
#pragma unroll
        for (int ni = 0; ni < 8; ni++)
#pragma unroll
            for (int q = 0; q < 4; q++) c[mi][ni][q] = 0.f;

    const int NPASS = DUAL ? 2 : 1;
    for (int pass = 0; pass < NPASS; pass++) {
        const float4* Asrc = (pass == 0) ? Am4 : Ax4;
        const float4* Wsrc = (pass == 0) ? Wl : Wr;
#pragma unroll
        for (int half = 0; half < 2; half++) {
            __syncthreads();   // previous compute consumers done before overwrite
            // ---- stage A half (128 x 64) and W half (128 x 64) as tf32 ----
            for (int i = tid; i < 2048; i += 256) {
                int r = i >> 4, kq = i & 15;     // 16 float4 per row-half
                int grow = row0 + r;
                float4 v = make_float4(0.f, 0.f, 0.f, 0.f);
                if (grow < n) v = Asrc[(size_t)grow * 32 + half * 16 + kq];
                uint32_t* pa = sA + r * SROW2 + kq * 4;
                pa[0] = cvt_tf32(v.x); pa[1] = cvt_tf32(v.y);
                pa[2] = cvt_tf32(v.z); pa[3] = cvt_tf32(v.w);
                float4 w = Wsrc[(size_t)r * 32 + half * 16 + kq];
                uint32_t* pw = sW + r * SROW2 + kq * 4;
                pw[0] = cvt_tf32(w.x); pw[1] = cvt_tf32(w.y);
                pw[2] = cvt_tf32(w.z); pw[3] = cvt_tf32(w.w);
            }
            __syncthreads();

            // ---- K loop: 8 steps of k8 over this half ----
#pragma unroll
            for (int k0 = 0; k0 < 64; k0 += 8) {
                uint32_t a[2][4];
#pragma unroll
                for (int mi = 0; mi < 2; mi++) {
                    int rb = wm * 32 + mi * 16;
                    const uint32_t* p0 = sA + (rb + g) * SROW2 + k0 + t;
                    const uint32_t* p1 = sA + (rb + 8 + g) * SROW2 + k0 + t;
                    a[mi][0] = p0[0]; a[mi][1] = p1[0];
                    a[mi][2] = p0[4]; a[mi][3] = p1[4];
                }
                uint32_t b[8][2];
#pragma unroll
                for (int ni = 0; ni < 8; ni++) {
                    const uint32_t* p = sW + (wn * 64 + ni * 8 + g) * SROW2 + k0 + t;
                    b[ni][0] = p[0]; b[ni][1] = p[4];
                }
#pragma unroll
                for (int mi = 0; mi < 2; mi++)
#pragma unroll
                    for (int ni = 0; ni < 8; ni++)
                        mma_tf32(c[mi][ni], a[mi], b[ni]);
            }
        }
    }
    __syncthreads();

    // ---- epilogue: bias + relu, float2 stores ----
#pragma unroll
    for (int mi = 0; mi < 2; mi++) {
#pragma unroll
        for (int h = 0; h < 2; h++) {
            int row = row0 + wm * 32 + mi * 16 + h * 8 + g;
            if (row >= n) continue;
            float* dst = Cout + (size_t)row * 128;
#pragma unroll
            for (int ni = 0; ni < 8; ni++) {
                int col = wn * 64 + ni * 8 + 2 * t;
                float2 o;
                o.x = fmaxf(c[mi][ni][h * 2 + 0] + sbias[col], 0.f);
                o.y = fmaxf(c[mi][ni][h * 2 + 1] + sbias[col + 1], 0.f);
                *(float2*)(dst + col) = o;
            }
        }
    }
}

// ================= head: out = sigmoid(g_agg @ Wm2^T + bm2) =================

__global__ void k_head(const float* __restrict__ Wm2,
                       const float* __restrict__ bm2, float* __restrict__ out, int n)
{
    __shared__ __align__(16) float sW[C_OUT * HDIM];
    __shared__ float sb[C_OUT];
    int t = threadIdx.x;
    for (int i = t; i < C_OUT * HDIM; i += blockDim.x) sW[i] = Wm2[i];
    if (t < C_OUT) sb[t] = bm2[t];
    __syncthreads();

    const float4* T1 = (const float4*)g_agg;
    int warp_id = (blockIdx.x * blockDim.x + t) >> 5;
    int lane = t & 31;

    for (int v = 0; v < 4; v++) {
        int node = warp_id * 4 + v;
        if (node >= n) return;
        float4 h = T1[(size_t)node * 32 + lane];
#pragma unroll
        for (int o = 0; o < C_OUT; o++) {
            float4 wv = *((const float4*)(sW + o * HDIM) + lane);
            float p = h.x * wv.x + h.y * wv.y + h.z * wv.z + h.w * wv.w;
            p += __shfl_xor_sync(0xFFFFFFFFu, p, 16);
            p += __shfl_xor_sync(0xFFFFFFFFu, p, 8);
            p += __shfl_xor_sync(0xFFFFFFFFu, p, 4);
            p += __shfl_xor_sync(0xFFFFFFFFu, p, 2);
            p += __shfl_xor_sync(0xFFFFFFFFu, p, 1);
            if (lane == o) {
                float z = p + sb[o];
                out[(size_t)node * C_OUT + o] = 1.f / (1.f + __expf(-z));
            }
        }
    }
}

// ================= launch =================

extern "C" void kernel_launch(void* const* d_in, const int* in_sizes, int n_in,
                              void* d_out, int out_size)
{
    const float* x   = (const float*)d_in[0];
    const int*   ei  = (const int*)d_in[1];
    const float* W1l = (const float*)d_in[2];
    const float* b1  = (const float*)d_in[3];
    const float* W1r = (const float*)d_in[4];
    const float* W2l = (const float*)d_in[5];
    const float* b2  = (const float*)d_in[6];
    const float* W2r = (const float*)d_in[7];
    const float* Wm1 = (const float*)d_in[8];
    const float* bm1 = (const float*)d_in[9];
    const float* Wm2 = (const float*)d_in[10];
    const float* bm2 = (const float*)d_in[11];
    float* out = (float*)d_out;

    int n = in_sizes[0] / HDIM;
    int e = in_sizes[1] / 2;
    int ntiles = (n + 127) / 128;

    const int SMEM_GEMM = 2 * 128 * SROW2 * 4;   // 69632 B -> 2 blocks/SM
    cudaFuncSetAttribute(k_mmagemm<0>, cudaFuncAttributeMaxDynamicSharedMemorySize, SMEM_GEMM);
    cudaFuncSetAttribute(k_mmagemm<1>, cudaFuncAttributeMaxDynamicSharedMemorySize, SMEM_GEMM);
    cudaFuncSetAttribute(k_mmagemm<2>, cudaFuncAttributeMaxDynamicSharedMemorySize, SMEM_GEMM);

    // CSR build
    k_zero_hist<<<(n + 255) / 256, 256>>>(n);
    k_hist<<<(e + 255) / 256, 256>>>(ei, e, n);
    int nb = (n + 2047) / 2048;
    k_scan1<<<nb, 512>>>(n);
    k_scan2<<<1, 128>>>(nb, n);
    k_scan3<<<nb, 512>>>(n);
    k_scatter<<<(e + 255) / 256, 256>>>(ei, e, n);

    int aggBlocks = (n + 7) / 8;

    // layer 1
    k_aggregate<true><<<aggBlocks, 256>>>((const float4*)x, n);
    k_mmagemm<0><<<ntiles, 256, SMEM_GEMM>>>((const float4*)x, (const float4*)W1l,
                                             (const float4*)W1r, b1, n);
    // layer 2
    k_aggregate<false><<<aggBlocks, 256>>>(nullptr, n);
    k_mmagemm<1><<<ntiles, 256, SMEM_GEMM>>>(nullptr, (const float4*)W2l,
                                             (const float4*)W2r, b2, n);
    // MLP layer
    k_mmagemm<2><<<ntiles, 256, SMEM_GEMM>>>(nullptr, (const float4*)Wm1, nullptr, bm1, n);
    // head
    int headBlocks = (n + 31) / 32;
    k_head<<<headBlocks, 256>>>(Wm2, bm2, out, n);
}

// round 14
// speedup vs baseline: 1.9771x; 1.0335x over previous
#include <cuda_runtime.h>
#include <cuda_fp16.h>
#include <math.h>
#include <stdint.h>

#define NMAX 100000
#define EMAX 1600000
#define HDIM 128
#define C_OUT 20

// ---- static device scratch (no allocation allowed) ----
__device__ float4 g_agg[(size_t)NMAX * HDIM / 4];   // fp32 aggregation / MLP temp
__device__ uint2  g_h16[(size_t)NMAX * HDIM / 4];   // fp16 activations (4 halves per uint2... 32 per row)
__device__ uint2  g_x16[(size_t)NMAX * HDIM / 4];   // fp16 copy of x
__device__ int    g_hist[NMAX];
__device__ int    g_rowptr[NMAX + 1];
__device__ int    g_wofs[NMAX];
__device__ int    g_srcs[EMAX];
__device__ int    g_bsum[128];

// ================= helpers =================

__device__ __forceinline__ uint32_t cvt_tf32(float f) {
    uint32_t u;
    asm("cvt.rna.tf32.f32 %0, %1;" : "=r"(u) : "f"(f));
    return u;
}

// D = A(16x8, tf32 row) * B(8x8, tf32 col) + C, fp32 accum
__device__ __forceinline__ void mma_tf32(float* c, const uint32_t* a, const uint32_t* b) {
    asm volatile(
        "mma.sync.aligned.m16n8k8.row.col.f32.tf32.tf32.f32 "
        "{%0,%1,%2,%3}, {%4,%5,%6,%7}, {%8,%9}, {%0,%1,%2,%3};"
        : "+f"(c[0]), "+f"(c[1]), "+f"(c[2]), "+f"(c[3])
        : "r"(a[0]), "r"(a[1]), "r"(a[2]), "r"(a[3]),
          "r"(b[0]), "r"(b[1]));
}

// ================= x -> fp16 convert =================

__global__ void k_cvt_x(const float4* __restrict__ x, int total) {
    int i = blockIdx.x * blockDim.x + threadIdx.x;
    if (i < total) {
        float4 v = x[i];
        uint2 o;
        half2 lo = __floats2half2_rn(v.x, v.y);
        half2 hi = __floats2half2_rn(v.z, v.w);
        o.x = *reinterpret_cast<uint32_t*>(&lo);
        o.y = *reinterpret_cast<uint32_t*>(&hi);
        g_x16[i] = o;
    }
}

// ================= CSR build (edge_index is device-resident int32) =================

__global__ void k_zero_hist(int n) {
    int i = blockIdx.x * blockDim.x + threadIdx.x;
    if (i < n) g_hist[i] = 0;
}

__global__ void k_hist(const int* __restrict__ ei, int e, int n) {
    int i = blockIdx.x * blockDim.x + threadIdx.x;
    if (i < e) {
        int d = ei[e + i];
        if ((unsigned)d < (unsigned)n) atomicAdd(&g_hist[d], 1);
    }
}

__global__ void k_scan1(int n) {
    __shared__ int sh[512];
    int b = blockIdx.x, t = threadIdx.x;
    int base = b * 2048 + t * 4;
    int s = 0;
#pragma unroll
    for (int i = 0; i < 4; i++) {
        int idx = base + i;
        if (idx < n) s += g_hist[idx];
    }
    sh[t] = s;
    __syncthreads();
    for (int off = 256; off > 0; off >>= 1) {
        if (t < off) sh[t] += sh[t + off];
        __syncthreads();
    }
    if (t == 0) g_bsum[b] = sh[0];
}

__global__ void k_scan2(int nb, int n) {
    __shared__ int sh[128];
    int t = threadIdx.x;
    int v = (t < nb) ? g_bsum[t] : 0;
    sh[t] = v;
    __syncthreads();
    for (int off = 1; off < 128; off <<= 1) {
        int a = (t >= off) ? sh[t - off] : 0;
        __syncthreads();
        sh[t] += a;
        __syncthreads();
    }
    int ex = (t == 0) ? 0 : sh[t - 1];
    if (t < nb) g_bsum[t] = ex;
    if (t == 127) g_rowptr[n] = sh[127];
}

__global__ void k_scan3(int n) {
    __shared__ int sh[512];
    int b = blockIdx.x, t = threadIdx.x;
    int base = b * 2048 + t * 4;
    int v[4];
    int s = 0;
#pragma unroll
    for (int i = 0; i < 4; i++) {
        int idx = base + i;
        v[i] = (idx < n) ? g_hist[idx] : 0;
        s += v[i];
    }
    sh[t] = s;
    __syncthreads();
    for (int off = 1; off < 512; off <<= 1) {
        int a = (t >= off) ? sh[t - off] : 0;
        __syncthreads();
        sh[t] += a;
        __syncthreads();
    }
    int run = g_bsum[b] + ((t == 0) ? 0 : sh[t - 1]);
#pragma unroll
    for (int i = 0; i < 4; i++) {
        int idx = base + i;
        if (idx < n) {
            g_rowptr[idx] = run;
            g_wofs[idx] = run;
            run += v[i];
        }
    }
}

__global__ void k_scatter(const int* __restrict__ ei, int e, int n) {
    int i = blockIdx.x * blockDim.x + threadIdx.x;
    if (i < e) {
        int d = ei[e + i];
        int s = ei[i];
        if ((unsigned)d < (unsigned)n && (unsigned)s < (unsigned)n) {
            int pos = atomicAdd(&g_wofs[d], 1);
            if ((unsigned)pos < (unsigned)EMAX) g_srcs[pos] = s;
        }
    }
}

// ================= mean aggregation: warp per node, fp16 gather =================
// Each lane loads 8 bytes (4 halves) per neighbor row: 32 lanes x 8B = 256B row.
// Accumulate fp32; output g_agg fp32 (feature f = lane*4+j, same order as before).

template <bool SRC_X>
__global__ void k_aggregate(int n) {
    const uint2* X = SRC_X ? (const uint2*)g_x16 : (const uint2*)g_h16;
    int w = (blockIdx.x * blockDim.x + threadIdx.x) >> 5;
    int lane = threadIdx.x & 31;
    if (w >= n) return;
    int beg = g_rowptr[w], end = g_rowptr[w + 1];
    float4 acc = make_float4(0.f, 0.f, 0.f, 0.f);
    int e = beg;
    for (; e + 1 < end; e += 2) {
        int s0 = g_srcs[e], s1 = g_srcs[e + 1];
        uint2 u0 = X[(size_t)s0 * 32 + lane];
        uint2 u1 = X[(size_t)s1 * 32 + lane];
        float2 a0 = __half22float2(*reinterpret_cast<half2*>(&u0.x));
        float2 b0 = __half22float2(*reinterpret_cast<half2*>(&u0.y));
        float2 a1 = __half22float2(*reinterpret_cast<half2*>(&u1.x));
        float2 b1 = __half22float2(*reinterpret_cast<half2*>(&u1.y));
        acc.x += a0.x + a1.x; acc.y += a0.y + a1.y;
        acc.z += b0.x + b1.x; acc.w += b0.y + b1.y;
    }
    if (e < end) {
        int s0 = g_srcs[e];
        uint2 u0 = X[(size_t)s0 * 32 + lane];
        float2 a0 = __half22float2(*reinterpret_cast<half2*>(&u0.x));
        float2 b0 = __half22float2(*reinterpret_cast<half2*>(&u0.y));
        acc.x += a0.x; acc.y += a0.y; acc.z += b0.x; acc.w += b0.y;
    }
    int cnt = end - beg;
    float inv = 1.0f / (float)(cnt > 0 ? cnt : 1);
    float4 r = make_float4(acc.x * inv, acc.y * inv, acc.z * inv, acc.w * inv);
    g_agg[(size_t)w * 32 + lane] = r;
}

// ================= tf32 mma.sync GEMM, K split in half, occupancy 2 =================
// C[128x128 tile] = relu( Am @ Wl^T [+ Ax @ Wr^T] + bias )
// MODE 0: Am=g_agg(fp32), Ax=g_x16(fp16) -> g_h16 (fp16)   layer 1
// MODE 1: Am=g_agg(fp32), Ax=g_h16(fp16) -> g_h16 (fp16)   layer 2 (in-place safe: block-local rows)
// MODE 2: Am=g_h16(fp16), single          -> g_agg (fp32)  MLP layer

#define SROW2 68   // padded half-K row length (floats), conflict-free fragment LDS

template <int MODE>
__global__ __launch_bounds__(256, 2) void k_mmagemm(
    const float4* __restrict__ Wl, const float4* __restrict__ Wr,
    const float* __restrict__ bias, int n)
{
    constexpr bool DUAL = (MODE != 2);
    extern __shared__ uint32_t smem[];           // sA[128*SROW2] then sW[128*SROW2]
    uint32_t* sA = smem;
    uint32_t* sW = smem + 128 * SROW2;
    __shared__ float sbias[128];

    int tid = threadIdx.x;
    int lane = tid & 31, wid = tid >> 5;
    int wm = wid >> 1, wn = wid & 1;             // warp grid 4 x 2
    int g = lane >> 2, t = lane & 3;
    int row0 = blockIdx.x * 128;

    if (tid < 128) sbias[tid] = bias[tid];

    float c[2][8][4];
#pragma unroll
    for (int mi = 0; mi < 2; mi++)
#pragma unroll
        for (int ni = 0; ni < 8; ni++)
#pragma unroll
            for (int q = 0; q < 4; q++) c[mi][ni][q] = 0.f;

    const int NPASS = DUAL ? 2 : 1;
    for (int pass = 0; pass < NPASS; pass++) {
        // pass A source: fp32 g_agg for pass 0 of DUAL; fp16 otherwise
        const bool aHalf = (MODE == 2) || (pass == 1);
        const float4* Af = (const float4*)g_agg;
        const uint2*  Ah = (MODE == 0) ? (const uint2*)g_x16 : (const uint2*)g_h16;
        const float4* Wsrc = (pass == 0) ? Wl : Wr;
#pragma unroll
        for (int half = 0; half < 2; half++) {
            __syncthreads();   // previous compute consumers done before overwrite
            // ---- stage A half (128 x 64) and W half (128 x 64) as tf32 ----
            for (int i = tid; i < 2048; i += 256) {
                int r = i >> 4, kq = i & 15;     // 16 chunks-of-4 per row-half
                int grow = row0 + r;
                uint32_t* pa = sA + r * SROW2 + kq * 4;
                if (aHalf) {
                    uint2 u = make_uint2(0u, 0u);
                    if (grow < n) u = Ah[(size_t)grow * 32 + half * 16 + kq];
                    float2 f0 = __half22float2(*reinterpret_cast<half2*>(&u.x));
                    float2 f1 = __half22float2(*reinterpret_cast<half2*>(&u.y));
                    pa[0] = cvt_tf32(f0.x); pa[1] = cvt_tf32(f0.y);
                    pa[2] = cvt_tf32(f1.x); pa[3] = cvt_tf32(f1.y);
                } else {
                    float4 v = make_float4(0.f, 0.f, 0.f, 0.f);
                    if (grow < n) v = Af[(size_t)grow * 32 + half * 16 + kq];
                    pa[0] = cvt_tf32(v.x); pa[1] = cvt_tf32(v.y);
                    pa[2] = cvt_tf32(v.z); pa[3] = cvt_tf32(v.w);
                }
                float4 w = Wsrc[(size_t)r * 32 + half * 16 + kq];
                uint32_t* pw = sW + r * SROW2 + kq * 4;
                pw[0] = cvt_tf32(w.x); pw[1] = cvt_tf32(w.y);
                pw[2] = cvt_tf32(w.z); pw[3] = cvt_tf32(w.w);
            }
            __syncthreads();

            // ---- K loop: 8 steps of k8 over this half ----
#pragma unroll
            for (int k0 = 0; k0 < 64; k0 += 8) {
                uint32_t a[2][4];
#pragma unroll
                for (int mi = 0; mi < 2; mi++) {
                    int rb = wm * 32 + mi * 16;
                    const uint32_t* p0 = sA + (rb + g) * SROW2 + k0 + t;
                    const uint32_t* p1 = sA + (rb + 8 + g) * SROW2 + k0 + t;
                    a[mi][0] = p0[0]; a[mi][1] = p1[0];
                    a[mi][2] = p0[4]; a[mi][3] = p1[4];
                }
                uint32_t b[8][2];
#pragma unroll
                for (int ni = 0; ni < 8; ni++) {
                    const uint32_t* p = sW + (wn * 64 + ni * 8 + g) * SROW2 + k0 + t;
                    b[ni][0] = p[0]; b[ni][1] = p[4];
                }
#pragma unroll
                for (int mi = 0; mi < 2; mi++)
#pragma unroll
                    for (int ni = 0; ni < 8; ni++)
                        mma_tf32(c[mi][ni], a[mi], b[ni]);
            }
        }
    }
    __syncthreads();

    // ---- epilogue: bias + relu ----
#pragma unroll
    for (int mi = 0; mi < 2; mi++) {
#pragma unroll
        for (int h = 0; h < 2; h++) {
            int row = row0 + wm * 32 + mi * 16 + h * 8 + g;
            if (row >= n) continue;
#pragma unroll
            for (int ni = 0; ni < 8; ni++) {
                int col = wn * 64 + ni * 8 + 2 * t;
                float ox = fmaxf(c[mi][ni][h * 2 + 0] + sbias[col], 0.f);
                float oy = fmaxf(c[mi][ni][h * 2 + 1] + sbias[col + 1], 0.f);
                if (MODE != 2) {
                    // fp16 store (4-byte aligned: col is even)
                    half2 hv = __floats2half2_rn(ox, oy);
                    *reinterpret_cast<uint32_t*>(
                        reinterpret_cast<half*>(g_h16) + (size_t)row * 128 + col) =
                        *reinterpret_cast<uint32_t*>(&hv);
                } else {
                    float2 o = make_float2(ox, oy);
                    *(float2*)((float*)g_agg + (size_t)row * 128 + col) = o;
                }
            }
        }
    }
}

// ================= head: out = sigmoid(g_agg @ Wm2^T + bm2) =================

__global__ void k_head(const float* __restrict__ Wm2,
                       const float* __restrict__ bm2, float* __restrict__ out, int n)
{
    __shared__ __align__(16) float sW[C_OUT * HDIM];
    __shared__ float sb[C_OUT];
    int t = threadIdx.x;
    for (int i = t; i < C_OUT * HDIM; i += blockDim.x) sW[i] = Wm2[i];
    if (t < C_OUT) sb[t] = bm2[t];
    __syncthreads();

    const float4* T1 = (const float4*)g_agg;
    int warp_id = (blockIdx.x * blockDim.x + t) >> 5;
    int lane = t & 31;

    for (int v = 0; v < 4; v++) {
        int node = warp_id * 4 + v;
        if (node >= n) return;
        float4 h = T1[(size_t)node * 32 + lane];
#pragma unroll
        for (int o = 0; o < C_OUT; o++) {
            float4 wv = *((const float4*)(sW + o * HDIM) + lane);
            float p = h.x * wv.x + h.y * wv.y + h.z * wv.z + h.w * wv.w;
            p += __shfl_xor_sync(0xFFFFFFFFu, p, 16);
            p += __shfl_xor_sync(0xFFFFFFFFu, p, 8);
            p += __shfl_xor_sync(0xFFFFFFFFu, p, 4);
            p += __shfl_xor_sync(0xFFFFFFFFu, p, 2);
            p += __shfl_xor_sync(0xFFFFFFFFu, p, 1);
            if (lane == o) {
                float z = p + sb[o];
                out[(size_t)node * C_OUT + o] = 1.f / (1.f + __expf(-z));
            }
        }
    }
}

// ================= launch =================

extern "C" void kernel_launch(void* const* d_in, const int* in_sizes, int n_in,
                              void* d_out, int out_size)
{
    const float* x   = (const float*)d_in[0];
    const int*   ei  = (const int*)d_in[1];
    const float* W1l = (const float*)d_in[2];
    const float* b1  = (const float*)d_in[3];
    const float* W1r = (const float*)d_in[4];
    const float* W2l = (const float*)d_in[5];
    const float* b2  = (const float*)d_in[6];
    const float* W2r = (const float*)d_in[7];
    const float* Wm1 = (const float*)d_in[8];
    const float* bm1 = (const float*)d_in[9];
    const float* Wm2 = (const float*)d_in[10];
    const float* bm2 = (const float*)d_in[11];
    float* out = (float*)d_out;

    int n = in_sizes[0] / HDIM;
    int e = in_sizes[1] / 2;
    int ntiles = (n + 127) / 128;

    const int SMEM_GEMM = 2 * 128 * SROW2 * 4;   // 69632 B -> 2 blocks/SM
    cudaFuncSetAttribute(k_mmagemm<0>, cudaFuncAttributeMaxDynamicSharedMemorySize, SMEM_GEMM);
    cudaFuncSetAttribute(k_mmagemm<1>, cudaFuncAttributeMaxDynamicSharedMemorySize, SMEM_GEMM);
    cudaFuncSetAttribute(k_mmagemm<2>, cudaFuncAttributeMaxDynamicSharedMemorySize, SMEM_GEMM);

    // x -> fp16 copy (also overlappable with CSR build on the same stream order)
    int total4 = n * 32;
    k_cvt_x<<<(total4 + 255) / 256, 256>>>((const float4*)x, total4);

    // CSR build
    k_zero_hist<<<(n + 255) / 256, 256>>>(n);
    k_hist<<<(e + 255) / 256, 256>>>(ei, e, n);
    int nb = (n + 2047) / 2048;
    k_scan1<<<nb, 512>>>(n);
    k_scan2<<<1, 128>>>(nb, n);
    k_scan3<<<nb, 512>>>(n);
    k_scatter<<<(e + 255) / 256, 256>>>(ei, e, n);

    int aggBlocks = (n + 7) / 8;

    // layer 1
    k_aggregate<true><<<aggBlocks, 256>>>(n);
    k_mmagemm<0><<<ntiles, 256, SMEM_GEMM>>>((const float4*)W1l, (const float4*)W1r, b1, n);
    // layer 2
    k_aggregate<false><<<aggBlocks, 256>>>(n);
    k_mmagemm<1><<<ntiles, 256, SMEM_GEMM>>>((const float4*)W2l, (const float4*)W2r, b2, n);
    // MLP layer
    k_mmagemm<2><<<ntiles, 256, SMEM_GEMM>>>((const float4*)Wm1, nullptr, bm1, n);
    // head
    int headBlocks = (n + 31) / 32;
    k_head<<<headBlocks, 256>>>(Wm2, bm2, out, n);
}

// round 15
// speedup vs baseline: 2.2139x; 1.1198x over previous
#include <cuda_runtime.h>
#include <cuda_fp16.h>
#include <math.h>
#include <stdint.h>

#define NMAX 100000
#define EMAX 1600000
#define HDIM 128
#define C_OUT 20

// ---- static device scratch (no allocation allowed) ----
__device__ float4 g_agg[(size_t)NMAX * HDIM / 4];   // fp32 aggregation / MLP temp
__device__ uint2  g_h16[(size_t)NMAX * HDIM / 4];   // fp16 activations (8 halves per uint2 pair-row)
__device__ uint2  g_x16[(size_t)NMAX * HDIM / 4];   // fp16 copy of x
__device__ int    g_hist[NMAX];
__device__ int    g_rowptr[NMAX + 1];
__device__ int    g_wofs[NMAX];
__device__ int    g_srcs[EMAX];
__device__ int    g_bsum[128];

// ================= helpers =================

__device__ __forceinline__ uint32_t pack_h2(float a, float b) {
    half2 h = __floats2half2_rn(a, b);
    return *reinterpret_cast<uint32_t*>(&h);
}

// D(16x8,f32) += A(16x16 f16 row) * B(16x8 f16 col); a = 4x b32 (half2), b = 2x b32
__device__ __forceinline__ void mma_f16(float* c, const uint32_t* a, const uint32_t* b) {
    asm volatile(
        "mma.sync.aligned.m16n8k16.row.col.f32.f16.f16.f32 "
        "{%0,%1,%2,%3}, {%4,%5,%6,%7}, {%8,%9}, {%0,%1,%2,%3};"
        : "+f"(c[0]), "+f"(c[1]), "+f"(c[2]), "+f"(c[3])
        : "r"(a[0]), "r"(a[1]), "r"(a[2]), "r"(a[3]),
          "r"(b[0]), "r"(b[1]));
}

// ================= x -> fp16 convert =================

__global__ void k_cvt_x(const float4* __restrict__ x, int total) {
    int i = blockIdx.x * blockDim.x + threadIdx.x;
    if (i < total) {
        float4 v = x[i];
        uint2 o;
        o.x = pack_h2(v.x, v.y);
        o.y = pack_h2(v.z, v.w);
        g_x16[i] = o;
    }
}

// ================= CSR build (edge_index is device-resident int32) =================

__global__ void k_zero_hist(int n) {
    int i = blockIdx.x * blockDim.x + threadIdx.x;
    if (i < n) g_hist[i] = 0;
}

__global__ void k_hist(const int* __restrict__ ei, int e, int n) {
    int i = blockIdx.x * blockDim.x + threadIdx.x;
    if (i < e) {
        int d = ei[e + i];
        if ((unsigned)d < (unsigned)n) atomicAdd(&g_hist[d], 1);
    }
}

__global__ void k_scan1(int n) {
    __shared__ int sh[512];
    int b = blockIdx.x, t = threadIdx.x;
    int base = b * 2048 + t * 4;
    int s = 0;
#pragma unroll
    for (int i = 0; i < 4; i++) {
        int idx = base + i;
        if (idx < n) s += g_hist[idx];
    }
    sh[t] = s;
    __syncthreads();
    for (int off = 256; off > 0; off >>= 1) {
        if (t < off) sh[t] += sh[t + off];
        __syncthreads();
    }
    if (t == 0) g_bsum[b] = sh[0];
}

__global__ void k_scan2(int nb, int n) {
    __shared__ int sh[128];
    int t = threadIdx.x;
    int v = (t < nb) ? g_bsum[t] : 0;
    sh[t] = v;
    __syncthreads();
    for (int off = 1; off < 128; off <<= 1) {
        int a = (t >= off) ? sh[t - off] : 0;
        __syncthreads();
        sh[t] += a;
        __syncthreads();
    }
    int ex = (t == 0) ? 0 : sh[t - 1];
    if (t < nb) g_bsum[t] = ex;
    if (t == 127) g_rowptr[n] = sh[127];
}

__global__ void k_scan3(int n) {
    __shared__ int sh[512];
    int b = blockIdx.x, t = threadIdx.x;
    int base = b * 2048 + t * 4;
    int v[4];
    int s = 0;
#pragma unroll
    for (int i = 0; i < 4; i++) {
        int idx = base + i;
        v[i] = (idx < n) ? g_hist[idx] : 0;
        s += v[i];
    }
    sh[t] = s;
    __syncthreads();
    for (int off = 1; off < 512; off <<= 1) {
        int a = (t >= off) ? sh[t - off] : 0;
        __syncthreads();
        sh[t] += a;
        __syncthreads();
    }
    int run = g_bsum[b] + ((t == 0) ? 0 : sh[t - 1]);
#pragma unroll
    for (int i = 0; i < 4; i++) {
        int idx = base + i;
        if (idx < n) {
            g_rowptr[idx] = run;
            g_wofs[idx] = run;
            run += v[i];
        }
    }
}

__global__ void k_scatter(const int* __restrict__ ei, int e, int n) {
    int i = blockIdx.x * blockDim.x + threadIdx.x;
    if (i < e) {
        int d = ei[e + i];
        int s = ei[i];
        if ((unsigned)d < (unsigned)n && (unsigned)s < (unsigned)n) {
            int pos = atomicAdd(&g_wofs[d], 1);
            if ((unsigned)pos < (unsigned)EMAX) g_srcs[pos] = s;
        }
    }
}

// ================= mean aggregation: warp per node, fp16 gather (R14 known-good) =================

template <bool SRC_X>
__global__ void k_aggregate(int n) {
    const uint2* X = SRC_X ? (const uint2*)g_x16 : (const uint2*)g_h16;
    int w = (blockIdx.x * blockDim.x + threadIdx.x) >> 5;
    int lane = threadIdx.x & 31;
    if (w >= n) return;
    int beg = g_rowptr[w], end = g_rowptr[w + 1];
    float4 acc = make_float4(0.f, 0.f, 0.f, 0.f);
    int e = beg;
    for (; e + 1 < end; e += 2) {
        int s0 = g_srcs[e], s1 = g_srcs[e + 1];
        uint2 u0 = X[(size_t)s0 * 32 + lane];
        uint2 u1 = X[(size_t)s1 * 32 + lane];
        float2 a0 = __half22float2(*reinterpret_cast<half2*>(&u0.x));
        float2 b0 = __half22float2(*reinterpret_cast<half2*>(&u0.y));
        float2 a1 = __half22float2(*reinterpret_cast<half2*>(&u1.x));
        float2 b1 = __half22float2(*reinterpret_cast<half2*>(&u1.y));
        acc.x += a0.x + a1.x; acc.y += a0.y + a1.y;
        acc.z += b0.x + b1.x; acc.w += b0.y + b1.y;
    }
    if (e < end) {
        int s0 = g_srcs[e];
        uint2 u0 = X[(size_t)s0 * 32 + lane];
        float2 a0 = __half22float2(*reinterpret_cast<half2*>(&u0.x));
        float2 b0 = __half22float2(*reinterpret_cast<half2*>(&u0.y));
        acc.x += a0.x; acc.y += a0.y; acc.z += b0.x; acc.w += b0.y;
    }
    int cnt = end - beg;
    float inv = 1.0f / (float)(cnt > 0 ? cnt : 1);
    float4 r = make_float4(acc.x * inv, acc.y * inv, acc.z * inv, acc.w * inv);
    g_agg[(size_t)w * 32 + lane] = r;
}

// ================= fp16 m16n8k16 GEMM, K split in half, occupancy 2 =================
// C[128x128 tile] = relu( Am @ Wl^T [+ Ax @ Wr^T] + bias ), fp32 accumulate.
// smem holds half2-packed fp16: row = 64 halves = 32 h2, padded stride 36 h2 (144B).
// MODE 0: Am=g_agg(fp32), Ax=g_x16(fp16) -> g_h16 (fp16)
// MODE 1: Am=g_agg(fp32), Ax=g_h16(fp16) -> g_h16 (fp16, block-local in-place safe)
// MODE 2: Am=g_h16(fp16), single          -> g_agg (fp32)

#define SROWH 36   // padded half-K row stride in half2 units

template <int MODE>
__global__ __launch_bounds__(256, 2) void k_mmagemm(
    const float4* __restrict__ Wl, const float4* __restrict__ Wr,
    const float* __restrict__ bias, int n)
{
    constexpr bool DUAL = (MODE != 2);
    extern __shared__ uint32_t smem[];           // sA[128*SROWH] then sW[128*SROWH] (h2 units)
    uint32_t* sA = smem;
    uint32_t* sW = smem + 128 * SROWH;
    __shared__ float sbias[128];

    int tid = threadIdx.x;
    int lane = tid & 31, wid = tid >> 5;
    int wm = wid >> 1, wn = wid & 1;             // warp grid 4 x 2
    int g = lane >> 2, t = lane & 3;
    int row0 = blockIdx.x * 128;

    if (tid < 128) sbias[tid] = bias[tid];

    float c[2][8][4];
#pragma unroll
    for (int mi = 0; mi < 2; mi++)
#pragma unroll
        for (int ni = 0; ni < 8; ni++)
#pragma unroll
            for (int q = 0; q < 4; q++) c[mi][ni][q] = 0.f;

    const int NPASS = DUAL ? 2 : 1;
    for (int pass = 0; pass < NPASS; pass++) {
        const bool aHalf = (MODE == 2) || (pass == 1);   // fp16 A source?
        const float4* Af = (const float4*)g_agg;
        const uint2*  Ah = (MODE == 0) ? (const uint2*)g_x16 : (const uint2*)g_h16;
        const float4* Wsrc = (pass == 0) ? Wl : Wr;
#pragma unroll
        for (int half = 0; half < 2; half++) {
            __syncthreads();   // previous compute consumers done before overwrite
            // ---- stage A half (128 x 64 halves) and W half as fp16 ----
            for (int i = tid; i < 2048; i += 256) {
                int r = i >> 4, kq = i & 15;     // kq indexes 16 float4 / 16 uint2 per row-half
                int grow = row0 + r;
                uint32_t* pa = sA + r * SROWH + kq * 2;
                if (aHalf) {
                    uint2 u = make_uint2(0u, 0u);
                    if (grow < n) u = Ah[(size_t)grow * 32 + half * 16 + kq];
                    pa[0] = u.x; pa[1] = u.y;            // raw fp16 copy
                } else {
                    float4 v = make_float4(0.f, 0.f, 0.f, 0.f);
                    if (grow < n) v = Af[(size_t)grow * 32 + half * 16 + kq];
                    pa[0] = pack_h2(v.x, v.y);
                    pa[1] = pack_h2(v.z, v.w);
                }
                float4 w = Wsrc[(size_t)r * 32 + half * 16 + kq];
                uint32_t* pw = sW + r * SROWH + kq * 2;
                pw[0] = pack_h2(w.x, w.y);
                pw[1] = pack_h2(w.z, w.w);
            }
            __syncthreads();

            // ---- K loop: 4 steps of k16 over this half (h2 step = 8) ----
#pragma unroll
            for (int k0 = 0; k0 < 32; k0 += 8) {
                uint32_t a[2][4];
#pragma unroll
                for (int mi = 0; mi < 2; mi++) {
                    int rb = wm * 32 + mi * 16;
                    const uint32_t* p0 = sA + (rb + g) * SROWH + k0 + t;
                    const uint32_t* p1 = sA + (rb + 8 + g) * SROWH + k0 + t;
                    a[mi][0] = p0[0]; a[mi][1] = p1[0];
                    a[mi][2] = p0[4]; a[mi][3] = p1[4];
                }
                uint32_t b[8][2];
#pragma unroll
                for (int ni = 0; ni < 8; ni++) {
                    const uint32_t* p = sW + (wn * 64 + ni * 8 + g) * SROWH + k0 + t;
                    b[ni][0] = p[0]; b[ni][1] = p[4];
                }
#pragma unroll
                for (int mi = 0; mi < 2; mi++)
#pragma unroll
                    for (int ni = 0; ni < 8; ni++)
                        mma_f16(c[mi][ni], a[mi], b[ni]);
            }
        }
    }
    __syncthreads();

    // ---- epilogue: bias + relu ----
#pragma unroll
    for (int mi = 0; mi < 2; mi++) {
#pragma unroll
        for (int h = 0; h < 2; h++) {
            int row = row0 + wm * 32 + mi * 16 + h * 8 + g;
            if (row >= n) continue;
#pragma unroll
            for (int ni = 0; ni < 8; ni++) {
                int col = wn * 64 + ni * 8 + 2 * t;
                float ox = fmaxf(c[mi][ni][h * 2 + 0] + sbias[col], 0.f);
                float oy = fmaxf(c[mi][ni][h * 2 + 1] + sbias[col + 1], 0.f);
                if (MODE != 2) {
                    *reinterpret_cast<uint32_t*>(
                        reinterpret_cast<half*>(g_h16) + (size_t)row * 128 + col) =
                        pack_h2(ox, oy);
                } else {
                    float2 o = make_float2(ox, oy);
                    *(float2*)((float*)g_agg + (size_t)row * 128 + col) = o;
                }
            }
        }
    }
}

// ================= head: out = sigmoid(g_agg @ Wm2^T + bm2) =================

__global__ void k_head(const float* __restrict__ Wm2,
                       const float* __restrict__ bm2, float* __restrict__ out, int n)
{
    __shared__ __align__(16) float sW[C_OUT * HDIM];
    __shared__ float sb[C_OUT];
    int t = threadIdx.x;
    for (int i = t; i < C_OUT * HDIM; i += blockDim.x) sW[i] = Wm2[i];
    if (t < C_OUT) sb[t] = bm2[t];
    __syncthreads();

    const float4* T1 = (const float4*)g_agg;
    int warp_id = (blockIdx.x * blockDim.x + t) >> 5;
    int lane = t & 31;

    for (int v = 0; v < 4; v++) {
        int node = warp_id * 4 + v;
        if (node >= n) return;
        float4 h = T1[(size_t)node * 32 + lane];
#pragma unroll
        for (int o = 0; o < C_OUT; o++) {
            float4 wv = *((const float4*)(sW + o * HDIM) + lane);
            float p = h.x * wv.x + h.y * wv.y + h.z * wv.z + h.w * wv.w;
            p += __shfl_xor_sync(0xFFFFFFFFu, p, 16);
            p += __shfl_xor_sync(0xFFFFFFFFu, p, 8);
            p += __shfl_xor_sync(0xFFFFFFFFu, p, 4);
            p += __shfl_xor_sync(0xFFFFFFFFu, p, 2);
            p += __shfl_xor_sync(0xFFFFFFFFu, p, 1);
            if (lane == o) {
                float z = p + sb[o];
                out[(size_t)node * C_OUT + o] = 1.f / (1.f + __expf(-z));
            }
        }
    }
}

// ================= launch =================

extern "C" void kernel_launch(void* const* d_in, const int* in_sizes, int n_in,
                              void* d_out, int out_size)
{
    const float* x   = (const float*)d_in[0];
    const int*   ei  = (const int*)d_in[1];
    const float* W1l = (const float*)d_in[2];
    const float* b1  = (const float*)d_in[3];
    const float* W1r = (const float*)d_in[4];
    const float* W2l = (const float*)d_in[5];
    const float* b2  = (const float*)d_in[6];
    const float* W2r = (const float*)d_in[7];
    const float* Wm1 = (const float*)d_in[8];
    const float* bm1 = (const float*)d_in[9];
    const float* Wm2 = (const float*)d_in[10];
    const float* bm2 = (const float*)d_in[11];
    float* out = (float*)d_out;

    int n = in_sizes[0] / HDIM;
    int e = in_sizes[1] / 2;
    int ntiles = (n + 127) / 128;

    const int SMEM_GEMM = 2 * 128 * SROWH * 4;   // 36864 B
    cudaFuncSetAttribute(k_mmagemm<0>, cudaFuncAttributeMaxDynamicSharedMemorySize, SMEM_GEMM);
    cudaFuncSetAttribute(k_mmagemm<1>, cudaFuncAttributeMaxDynamicSharedMemorySize, SMEM_GEMM);
    cudaFuncSetAttribute(k_mmagemm<2>, cudaFuncAttributeMaxDynamicSharedMemorySize, SMEM_GEMM);

    // x -> fp16 copy
    int total4 = n * 32;
    k_cvt_x<<<(total4 + 255) / 256, 256>>>((const float4*)x, total4);

    // CSR build
    k_zero_hist<<<(n + 255) / 256, 256>>>(n);
    k_hist<<<(e + 255) / 256, 256>>>(ei, e, n);
    int nb = (n + 2047) / 2048;
    k_scan1<<<nb, 512>>>(n);
    k_scan2<<<1, 128>>>(nb, n);
    k_scan3<<<nb, 512>>>(n);
    k_scatter<<<(e + 255) / 256, 256>>>(ei, e, n);

    int aggBlocks = (n + 7) / 8;

    // layer 1
    k_aggregate<true><<<aggBlocks, 256>>>(n);
    k_mmagemm<0><<<ntiles, 256, SMEM_GEMM>>>((const float4*)W1l, (const float4*)W1r, b1, n);
    // layer 2
    k_aggregate<false><<<aggBlocks, 256>>>(n);
    k_mmagemm<1><<<ntiles, 256, SMEM_GEMM>>>((const float4*)W2l, (const float4*)W2r, b2, n);
    // MLP layer
    k_mmagemm<2><<<ntiles, 256, SMEM_GEMM>>>((const float4*)Wm1, nullptr, bm1, n);
    // head
    int headBlocks = (n + 31) / 32;
    k_head<<<headBlocks, 256>>>(Wm2, bm2, out, n);
}

// round 17
// speedup vs baseline: 2.2756x; 1.0278x over previous
#include <cuda_runtime.h>
#include <cuda_fp16.h>
#include <math.h>
#include <stdint.h>

#define NMAX 100000
#define EMAX 1600000
#define HDIM 128
#define C_OUT 20

// ---- static device scratch (no allocation allowed) ----
// fp16 row = 128 halves = 32 uint2  =>  arrays sized NMAX * HDIM / 4 uint2.
__device__ uint2  g_agg16[(size_t)NMAX * HDIM / 4]; // fp16 aggregated mean
__device__ uint2  g_h16[(size_t)NMAX * HDIM / 4];   // fp16 activations
__device__ uint2  g_x16[(size_t)NMAX * HDIM / 4];   // fp16 copy of x
__device__ uint2  g_t16[(size_t)NMAX * HDIM / 4];   // fp16 MLP output (head input)
__device__ uint2  g_w16[5 * 4096];                  // fp16 weights: W1l,W1r,W2l,W2r,Wm1
__device__ int    g_hist[NMAX];
__device__ int    g_rowptr[NMAX + 1];
__device__ int    g_wofs[NMAX];
__device__ int    g_srcs[EMAX];
__device__ int    g_bsum[128];

// ================= helpers =================

__device__ __forceinline__ uint32_t pack_h2(float a, float b) {
    half2 h = __floats2half2_rn(a, b);
    return *reinterpret_cast<uint32_t*>(&h);
}

// D(16x8,f32) += A(16x16 f16 row) * B(16x8 f16 col)
__device__ __forceinline__ void mma_f16(float* c, const uint32_t* a, const uint32_t* b) {
    asm volatile(
        "mma.sync.aligned.m16n8k16.row.col.f32.f16.f16.f32 "
        "{%0,%1,%2,%3}, {%4,%5,%6,%7}, {%8,%9}, {%0,%1,%2,%3};"
        : "+f"(c[0]), "+f"(c[1]), "+f"(c[2]), "+f"(c[3])
        : "r"(a[0]), "r"(a[1]), "r"(a[2]), "r"(a[3]),
          "r"(b[0]), "r"(b[1]));
}

// ================= converts =================

__global__ void k_cvt_x(const float4* __restrict__ x, int total) {
    int i = blockIdx.x * blockDim.x + threadIdx.x;
    if (i < total) {
        float4 v = x[i];
        uint2 o;
        o.x = pack_h2(v.x, v.y);
        o.y = pack_h2(v.z, v.w);
        g_x16[i] = o;
    }
}

// convert 5 weight matrices (each 4096 float4) to fp16
__global__ void k_cvt_w(const float4* __restrict__ w0, const float4* __restrict__ w1,
                        const float4* __restrict__ w2, const float4* __restrict__ w3,
                        const float4* __restrict__ w4) {
    int i = blockIdx.x * blockDim.x + threadIdx.x;
    if (i >= 5 * 4096) return;
    int m = i >> 12, j = i & 4095;
    const float4* src = (m == 0) ? w0 : (m == 1) ? w1 : (m == 2) ? w2 : (m == 3) ? w3 : w4;
    float4 v = src[j];
    uint2 o;
    o.x = pack_h2(v.x, v.y);
    o.y = pack_h2(v.z, v.w);
    g_w16[i] = o;
}

// ================= CSR build (edge_index is device-resident int32) =================

__global__ void k_zero_hist(int n) {
    int i = blockIdx.x * blockDim.x + threadIdx.x;
    if (i < n) g_hist[i] = 0;
}

__global__ void k_hist(const int* __restrict__ ei, int e, int n) {
    int i = blockIdx.x * blockDim.x + threadIdx.x;
    if (i < e) {
        int d = ei[e + i];
        if ((unsigned)d < (unsigned)n) atomicAdd(&g_hist[d], 1);
    }
}

__global__ void k_scan1(int n) {
    __shared__ int sh[512];
    int b = blockIdx.x, t = threadIdx.x;
    int base = b * 2048 + t * 4;
    int s = 0;
#pragma unroll
    for (int i = 0; i < 4; i++) {
        int idx = base + i;
        if (idx < n) s += g_hist[idx];
    }
    sh[t] = s;
    __syncthreads();
    for (int off = 256; off > 0; off >>= 1) {
        if (t < off) sh[t] += sh[t + off];
        __syncthreads();
    }
    if (t == 0) g_bsum[b] = sh[0];
}

__global__ void k_scan2(int nb, int n) {
    __shared__ int sh[128];
    int t = threadIdx.x;
    int v = (t < nb) ? g_bsum[t] : 0;
    sh[t] = v;
    __syncthreads();
    for (int off = 1; off < 128; off <<= 1) {
        int a = (t >= off) ? sh[t - off] : 0;
        __syncthreads();
        sh[t] += a;
        __syncthreads();
    }
    int ex = (t == 0) ? 0 : sh[t - 1];
    if (t < nb) g_bsum[t] = ex;
    if (t == 127) g_rowptr[n] = sh[127];
}

__global__ void k_scan3(int n) {
    __shared__ int sh[512];
    int b = blockIdx.x, t = threadIdx.x;
    int base = b * 2048 + t * 4;
    int v[4];
    int s = 0;
#pragma unroll
    for (int i = 0; i < 4; i++) {
        int idx = base + i;
        v[i] = (idx < n) ? g_hist[idx] : 0;
        s += v[i];
    }
    sh[t] = s;
    __syncthreads();
    for (int off = 1; off < 512; off <<= 1) {
        int a = (t >= off) ? sh[t - off] : 0;
        __syncthreads();
        sh[t] += a;
        __syncthreads();
    }
    int run = g_bsum[b] + ((t == 0) ? 0 : sh[t - 1]);
#pragma unroll
    for (int i = 0; i < 4; i++) {
        int idx = base + i;
        if (idx < n) {
            g_rowptr[idx] = run;
            g_wofs[idx] = run;
            run += v[i];
        }
    }
}

__global__ void k_scatter(const int* __restrict__ ei, int e, int n) {
    int i = blockIdx.x * blockDim.x + threadIdx.x;
    if (i < e) {
        int d = ei[e + i];
        int s = ei[i];
        if ((unsigned)d < (unsigned)n && (unsigned)s < (unsigned)n) {
            int pos = atomicAdd(&g_wofs[d], 1);
            if ((unsigned)pos < (unsigned)EMAX) g_srcs[pos] = s;
        }
    }
}

// ================= mean aggregation: warp per node, fp16 gather + fp16 store =================

template <bool SRC_X>
__global__ void k_aggregate(int n) {
    const uint2* X = SRC_X ? (const uint2*)g_x16 : (const uint2*)g_h16;
    int w = (blockIdx.x * blockDim.x + threadIdx.x) >> 5;
    int lane = threadIdx.x & 31;
    if (w >= n) return;
    int beg = g_rowptr[w], end = g_rowptr[w + 1];
    float4 acc = make_float4(0.f, 0.f, 0.f, 0.f);
    int e = beg;
    for (; e + 1 < end; e += 2) {
        int s0 = g_srcs[e], s1 = g_srcs[e + 1];
        uint2 u0 = X[(size_t)s0 * 32 + lane];
        uint2 u1 = X[(size_t)s1 * 32 + lane];
        float2 a0 = __half22float2(*reinterpret_cast<half2*>(&u0.x));
        float2 b0 = __half22float2(*reinterpret_cast<half2*>(&u0.y));
        float2 a1 = __half22float2(*reinterpret_cast<half2*>(&u1.x));
        float2 b1 = __half22float2(*reinterpret_cast<half2*>(&u1.y));
        acc.x += a0.x + a1.x; acc.y += a0.y + a1.y;
        acc.z += b0.x + b1.x; acc.w += b0.y + b1.y;
    }
    if (e < end) {
        int s0 = g_srcs[e];
        uint2 u0 = X[(size_t)s0 * 32 + lane];
        float2 a0 = __half22float2(*reinterpret_cast<half2*>(&u0.x));
        float2 b0 = __half22float2(*reinterpret_cast<half2*>(&u0.y));
        acc.x += a0.x; acc.y += a0.y; acc.z += b0.x; acc.w += b0.y;
    }
    int cnt = end - beg;
    float inv = 1.0f / (float)(cnt > 0 ? cnt : 1);
    uint2 o;
    o.x = pack_h2(acc.x * inv, acc.y * inv);
    o.y = pack_h2(acc.z * inv, acc.w * inv);
    g_agg16[(size_t)w * 32 + lane] = o;
}

// ================= fp16 m16n8k16 GEMM, full-K tiles, occupancy 2 =================
// C[128x128 tile] = relu( Am @ Wl^T [+ Ax @ Wr^T] + bias ), fp32 accumulate.
// All sources fp16 -> staging is a raw uint2 copy. smem: 2 x 128 x 68 words = 69.6 KB.
// MODE 0: Am=g_agg16, Ax=g_x16, W=g_w16[0],[1] -> g_h16
// MODE 1: Am=g_agg16, Ax=g_h16, W=g_w16[2],[3] -> g_h16 (block-local in-place safe)
// MODE 2: Am=g_h16,   single,   W=g_w16[4]     -> g_t16

#define SROWF 68   // full-K row stride in h2 units (64 data + 4 pad)

template <int MODE>
__global__ __launch_bounds__(256, 2) void k_mmagemm(const float* __restrict__ bias, int n)
{
    constexpr bool DUAL = (MODE != 2);
    extern __shared__ uint32_t smem[];           // sA[128*SROWF] then sW[128*SROWF]
    uint32_t* sA = smem;
    uint32_t* sW = smem + 128 * SROWF;
    __shared__ float sbias[128];

    int tid = threadIdx.x;
    int lane = tid & 31, wid = tid >> 5;
    int wm = wid >> 1, wn = wid & 1;             // warp grid 4 x 2
    int g = lane >> 2, t = lane & 3;
    int row0 = blockIdx.x * 128;

    if (tid < 128) sbias[tid] = bias[tid];

    float c[2][8][4];
#pragma unroll
    for (int mi = 0; mi < 2; mi++)
#pragma unroll
        for (int ni = 0; ni < 8; ni++)
#pragma unroll
            for (int q = 0; q < 4; q++) c[mi][ni][q] = 0.f;

    const int NPASS = DUAL ? 2 : 1;
    for (int pass = 0; pass < NPASS; pass++) {
        const uint2* Asrc = (pass == 0)
            ? ((MODE == 2) ? (const uint2*)g_h16 : (const uint2*)g_agg16)
            : ((MODE == 0) ? (const uint2*)g_x16 : (const uint2*)g_h16);
        const uint2* Wsrc = (const uint2*)g_w16 +
            ((MODE == 0) ? (pass == 0 ? 0 : 1) :
             (MODE == 1) ? (pass == 0 ? 2 : 3) : 4) * 4096;

        __syncthreads();   // previous pass consumers done before overwrite
        // ---- stage A (128 x 128 halves) and W, raw fp16 copies ----
        for (int i = tid; i < 4096; i += 256) {
            int r = i >> 5, kq = i & 31;         // 32 uint2 per row
            int grow = row0 + r;
            uint2 u = make_uint2(0u, 0u);
            if (grow < n) u = Asrc[(size_t)grow * 32 + kq];
            uint32_t* pa = sA + r * SROWF + kq * 2;
            pa[0] = u.x; pa[1] = u.y;
            uint2 w = Wsrc[i];
            uint32_t* pw = sW + r * SROWF + kq * 2;
            pw[0] = w.x; pw[1] = w.y;
        }
        __syncthreads();

        // ---- K loop: 8 steps of k16 (h2 step = 8) ----
#pragma unroll
        for (int k0 = 0; k0 < 64; k0 += 8) {
            uint32_t a[2][4];
#pragma unroll
            for (int mi = 0; mi < 2; mi++) {
                int rb = wm * 32 + mi * 16;
                const uint32_t* p0 = sA + (rb + g) * SROWF + k0 + t;
                const uint32_t* p1 = sA + (rb + 8 + g) * SROWF + k0 + t;
                a[mi][0] = p0[0]; a[mi][1] = p1[0];
                a[mi][2] = p0[4]; a[mi][3] = p1[4];
            }
            uint32_t b[8][2];
#pragma unroll
            for (int ni = 0; ni < 8; ni++) {
                const uint32_t* p = sW + (wn * 64 + ni * 8 + g) * SROWF + k0 + t;
                b[ni][0] = p[0]; b[ni][1] = p[4];
            }
#pragma unroll
            for (int mi = 0; mi < 2; mi++)
#pragma unroll
                for (int ni = 0; ni < 8; ni++)
                    mma_f16(c[mi][ni], a[mi], b[ni]);
        }
    }
    __syncthreads();

    // ---- epilogue: bias + relu -> fp16 ----
    uint2* Dst = (MODE == 2) ? (uint2*)g_t16 : (uint2*)g_h16;
#pragma unroll
    for (int mi = 0; mi < 2; mi++) {
#pragma unroll
        for (int h = 0; h < 2; h++) {
            int row = row0 + wm * 32 + mi * 16 + h * 8 + g;
            if (row >= n) continue;
#pragma unroll
            for (int ni = 0; ni < 8; ni++) {
                int col = wn * 64 + ni * 8 + 2 * t;
                float ox = fmaxf(c[mi][ni][h * 2 + 0] + sbias[col], 0.f);
                float oy = fmaxf(c[mi][ni][h * 2 + 1] + sbias[col + 1], 0.f);
                *reinterpret_cast<uint32_t*>(
                    reinterpret_cast<half*>(Dst) + (size_t)row * 128 + col) =
                    pack_h2(ox, oy);
            }
        }
    }
}

// ================= head: out = sigmoid(g_t16 @ Wm2^T + bm2) =================

__global__ void k_head(const float* __restrict__ Wm2,
                       const float* __restrict__ bm2, float* __restrict__ out, int n)
{
    __shared__ __align__(16) float sW[C_OUT * HDIM];
    __shared__ float sb[C_OUT];
    int t = threadIdx.x;
    for (int i = t; i < C_OUT * HDIM; i += blockDim.x) sW[i] = Wm2[i];
    if (t < C_OUT) sb[t] = bm2[t];
    __syncthreads();

    const uint2* T1 = (const uint2*)g_t16;
    int warp_id = (blockIdx.x * blockDim.x + t) >> 5;
    int lane = t & 31;

    for (int v = 0; v < 4; v++) {
        int node = warp_id * 4 + v;
        if (node >= n) return;
        uint2 u = T1[(size_t)node * 32 + lane];
        float2 h0 = __half22float2(*reinterpret_cast<half2*>(&u.x));
        float2 h1 = __half22float2(*reinterpret_cast<half2*>(&u.y));
#pragma unroll
        for (int o = 0; o < C_OUT; o++) {
            float4 wv = *((const float4*)(sW + o * HDIM) + lane);
            float p = h0.x * wv.x + h0.y * wv.y + h1.x * wv.z + h1.y * wv.w;
            p += __shfl_xor_sync(0xFFFFFFFFu, p, 16);
            p += __shfl_xor_sync(0xFFFFFFFFu, p, 8);
            p += __shfl_xor_sync(0xFFFFFFFFu, p, 4);
            p += __shfl_xor_sync(0xFFFFFFFFu, p, 2);
            p += __shfl_xor_sync(0xFFFFFFFFu, p, 1);
            if (lane == o) {
                float z = p + sb[o];
                out[(size_t)node * C_OUT + o] = 1.f / (1.f + __expf(-z));
            }
        }
    }
}

// ================= launch =================

extern "C" void kernel_launch(void* const* d_in, const int* in_sizes, int n_in,
                              void* d_out, int out_size)
{
    const float* x   = (const float*)d_in[0];
    const int*   ei  = (const int*)d_in[1];
    const float* W1l = (const float*)d_in[2];
    const float* b1  = (const float*)d_in[3];
    const float* W1r = (const float*)d_in[4];
    const float* W2l = (const float*)d_in[5];
    const float* b2  = (const float*)d_in[6];
    const float* W2r = (const float*)d_in[7];
    const float* Wm1 = (const float*)d_in[8];
    const float* bm1 = (const float*)d_in[9];
    const float* Wm2 = (const float*)d_in[10];
    const float* bm2 = (const float*)d_in[11];
    float* out = (float*)d_out;

    int n = in_sizes[0] / HDIM;
    int e = in_sizes[1] / 2;
    int ntiles = (n + 127) / 128;

    const int SMEM_GEMM = 2 * 128 * SROWF * 4;   // 69632 B -> 2 blocks/SM
    cudaFuncSetAttribute(k_mmagemm<0>, cudaFuncAttributeMaxDynamicSharedMemorySize, SMEM_GEMM);
    cudaFuncSetAttribute(k_mmagemm<1>, cudaFuncAttributeMaxDynamicSharedMemorySize, SMEM_GEMM);
    cudaFuncSetAttribute(k_mmagemm<2>, cudaFuncAttributeMaxDynamicSharedMemorySize, SMEM_GEMM);

    // converts (x and weights -> fp16)
    int total4 = n * 32;
    k_cvt_x<<<(total4 + 255) / 256, 256>>>((const float4*)x, total4);
    k_cvt_w<<<(5 * 4096 + 255) / 256, 256>>>((const float4*)W1l, (const float4*)W1r,
                                             (const float4*)W2l, (const float4*)W2r,
                                             (const float4*)Wm1);

    // CSR build
    k_zero_hist<<<(n + 255) / 256, 256>>>(n);
    k_hist<<<(e + 255) / 256, 256>>>(ei, e, n);
    int nb = (n + 2047) / 2048;
    k_scan1<<<nb, 512>>>(n);
    k_scan2<<<1, 128>>>(nb, n);
    k_scan3<<<nb, 512>>>(n);
    k_scatter<<<(e + 255) / 256, 256>>>(ei, e, n);

    int aggBlocks = (n + 7) / 8;

    // layer 1
    k_aggregate<true><<<aggBlocks, 256>>>(n);
    k_mmagemm<0><<<ntiles, 256, SMEM_GEMM>>>(b1, n);
    // layer 2
    k_aggregate<false><<<aggBlocks, 256>>>(n);
    k_mmagemm<1><<<ntiles, 256, SMEM_GEMM>>>(b2, n);
    // MLP layer
    k_mmagemm<2><<<ntiles, 256, SMEM_GEMM>>>(bm1, n);
    // head
    int headBlocks = (n + 31) / 32;
    k_head<<<headBlocks, 256>>>(Wm2, bm2, out, n);
}